// round 14
// baseline (speedup 1.0000x reference)
#include <cuda_runtime.h>
#include <cuda_bf16.h>
#include <cuda_fp16.h>
#include <math.h>
#include <stdint.h>

#define B_  8
#define S_  512
#define D_  1024
#define H_  16
#define DH_ 64
#define BH_ 128

// ---------------- scratch (device globals; no runtime allocation) ----------------
__device__ float g_sc [(size_t)BH_*S_*S_];            // fp32 scores
__device__ float g_att[(size_t)B_*S_*D_];             // attention out, concat [B,S,D]
__device__ float g_dv [(size_t)B_*S_*S_];             // exp(sigmoid(pdiff))
__device__ __nv_bfloat16 g_qhh[(size_t)BH_*S_*DH_], g_qhl[(size_t)BH_*S_*DH_];
__device__ __nv_bfloat16 g_khh[(size_t)BH_*S_*DH_], g_khl[(size_t)BH_*S_*DH_];
__device__ __half        g_vhh[(size_t)BH_*S_*DH_], g_vhl[(size_t)BH_*S_*DH_];   // fp16
__device__ __half        g_phi[(size_t)BH_*S_*S_],  g_plo[(size_t)BH_*S_*S_];    // fp16

// ======================= warp-level MMA + ldmatrix ================================
__device__ __forceinline__ void mma_bf16(float* c, uint32_t a0, uint32_t a1,
                                         uint32_t a2, uint32_t a3,
                                         uint32_t b0, uint32_t b1) {
    asm volatile(
        "mma.sync.aligned.m16n8k16.row.col.f32.bf16.bf16.f32 "
        "{%0,%1,%2,%3}, {%4,%5,%6,%7}, {%8,%9}, {%0,%1,%2,%3};"
        : "+f"(c[0]), "+f"(c[1]), "+f"(c[2]), "+f"(c[3])
        : "r"(a0), "r"(a1), "r"(a2), "r"(a3), "r"(b0), "r"(b1));
}
__device__ __forceinline__ void mma_f16(float* c, uint32_t a0, uint32_t a1,
                                        uint32_t a2, uint32_t a3,
                                        uint32_t b0, uint32_t b1) {
    asm volatile(
        "mma.sync.aligned.m16n8k16.row.col.f32.f16.f16.f32 "
        "{%0,%1,%2,%3}, {%4,%5,%6,%7}, {%8,%9}, {%0,%1,%2,%3};"
        : "+f"(c[0]), "+f"(c[1]), "+f"(c[2]), "+f"(c[3])
        : "r"(a0), "r"(a1), "r"(a2), "r"(a3), "r"(b0), "r"(b1));
}
__device__ __forceinline__ uint32_t smem_u32(const void* p) {
    uint32_t a;
    asm("{ .reg .u64 t; cvta.to.shared.u64 t, %1; cvt.u32.u64 %0, t; }" : "=r"(a) : "l"(p));
    return a;
}
__device__ __forceinline__ void ldsm_x4(uint32_t& r0, uint32_t& r1, uint32_t& r2,
                                        uint32_t& r3, uint32_t a) {
    asm volatile("ldmatrix.sync.aligned.m8n8.x4.shared.b16 {%0,%1,%2,%3}, [%4];"
                 : "=r"(r0), "=r"(r1), "=r"(r2), "=r"(r3) : "r"(a));
}
__device__ __forceinline__ void ldsm_x2(uint32_t& r0, uint32_t& r1, uint32_t a) {
    asm volatile("ldmatrix.sync.aligned.m8n8.x2.shared.b16 {%0,%1}, [%2];"
                 : "=r"(r0), "=r"(r1) : "r"(a));
}
__device__ __forceinline__ uint32_t pack_bf16(float x, float y) {
    __nv_bfloat162 t = __floats2bfloat162_rn(x, y);
    return *(uint32_t*)&t;
}
__device__ __forceinline__ uint32_t pack_f16(float x, float y) {
    __half2 t = __floats2half2_rn(x, y);
    return *(uint32_t*)&t;
}
__device__ __forceinline__ void split4(float4 v, uint32_t& h0, uint32_t& h1,
                                       uint32_t& l0, uint32_t& l1) {
    h0 = pack_bf16(v.x, v.y);
    h1 = pack_bf16(v.z, v.w);
    __nv_bfloat162 hh0 = *(__nv_bfloat162*)&h0;
    __nv_bfloat162 hh1 = *(__nv_bfloat162*)&h1;
    l0 = pack_bf16(v.x - __bfloat162float(hh0.x), v.y - __bfloat162float(hh0.y));
    l1 = pack_bf16(v.z - __bfloat162float(hh1.x), v.w - __bfloat162float(hh1.y));
}
__device__ __forceinline__ void split4h(float4 v, uint32_t& h0, uint32_t& h1,
                                        uint32_t& l0, uint32_t& l1) {
    __half2 a = __floats2half2_rn(v.x, v.y);
    __half2 b = __floats2half2_rn(v.z, v.w);
    h0 = *(uint32_t*)&a;
    h1 = *(uint32_t*)&b;
    __half2 la = __floats2half2_rn(v.x - __half2float(__low2half(a)),
                                   v.y - __half2float(__high2half(a)));
    __half2 lb = __floats2half2_rn(v.z - __half2float(__low2half(b)),
                                   v.w - __half2float(__high2half(b)));
    l0 = *(uint32_t*)&la;
    l1 = *(uint32_t*)&lb;
}

// ==================================================================================
// Double-buffered emulated-fp32 GEMM, 512 threads, LDSM fragments.
// EMU=0: bf16 3-pass; EMU=1: fp16 2-pass.  NT = N-tile/32 (4 -> 128-wide, 2 -> 64).
// Block 128(M) x 32*NT(N), BK=32, warp grid 4x4, warp tile 32 x 8*NT.
// ==================================================================================
#define PADW 20
#define STG  10240

template<bool PAIR, int EMU, int NT>
__device__ __forceinline__ void gemm_body(const float* __restrict__ A,
                                          const float* __restrict__ W,
                                          const float* __restrict__ bias,
                                          float* outF, void* outHv, void* outLv,
                                          int m0, int n0, uint32_t* dsm)
{
    int tid = threadIdx.x, lane = tid & 31, wid = tid >> 5;
    int wm = wid >> 2, wn = wid & 3;
    int lq = lane >> 2, tq = lane & 3;

    uint32_t sbase = smem_u32(dsm);
    int sub     = lane >> 3;
    int arow_t  = ((sub & 1) << 3) + (lane & 7);
    int aword_t = (sub >> 1) << 2;
    int brow_t  = lane & 7;
    int bword_t = ((lane >> 3) & 1) << 2;

    float acc[2][NT][4];
    #pragma unroll
    for (int mt = 0; mt < 2; mt++)
        #pragma unroll
        for (int nt = 0; nt < NT; nt++)
            #pragma unroll
            for (int e = 0; e < 4; e++) acc[mt][nt][e] = 0.f;

    // A: 1024 uint4 slots (2/thread). B: NT*256 slots (NT/2 per thread).
    int arow[2], acq[2], aof[2];
    #pragma unroll
    for (int r = 0; r < 2; r++) {
        int g = tid + r * 512;
        arow[r] = g >> 3; acq[r] = g & 7;
        aof[r] = arow[r] * PADW + acq[r] * 2;
    }
    int brow[2], bcq[2], bof[2];
    #pragma unroll
    for (int r = 0; r < NT / 2; r++) {
        int g = tid + r * 512;
        brow[r] = g >> 3; bcq[r] = g & 7;
        bof[r] = brow[r] * PADW + bcq[r] * 2;
    }

    float4 va[2], vb[2];
    auto fetch = [&](int kc) {
        int k0 = kc * 32;
        #pragma unroll
        for (int r = 0; r < 2; r++)
            va[r] = *(const float4*)(A + (size_t)(m0 + arow[r]) * D_ + k0 + acq[r] * 4);
        #pragma unroll
        for (int r = 0; r < NT / 2; r++)
            vb[r] = *(const float4*)(W + (size_t)(n0 + brow[r]) * D_ + k0 + bcq[r] * 4);
    };
    auto cvtstore = [&](uint32_t* base) {
        #pragma unroll
        for (int r = 0; r < 2; r++) {
            uint32_t h0, h1, l0, l1;
            if (EMU == 0) split4 (va[r], h0, h1, l0, l1);
            else          split4h(va[r], h0, h1, l0, l1);
            base[aof[r]]        = h0; base[aof[r] + 1]        = h1;
            base[2560 + aof[r]] = l0; base[2560 + aof[r] + 1] = l1;
        }
        #pragma unroll
        for (int r = 0; r < NT / 2; r++) {
            uint32_t h0, h1, l0, l1;
            if (EMU == 0) split4 (vb[r], h0, h1, l0, l1);
            else          split4h(vb[r], h0, h1, l0, l1);
            base[5120 + bof[r]] = h0; base[5120 + bof[r] + 1] = h1;
            if (EMU == 0) {
                base[7680 + bof[r]] = l0; base[7680 + bof[r] + 1] = l1;
            }
        }
    };

    fetch(0);
    cvtstore(dsm);
    int stage = 0;

    for (int kc = 0; kc < 32; kc++) {
        __syncthreads();
        if (kc < 31) fetch(kc + 1);
        uint32_t sb = sbase + stage * (STG * 4);
        #pragma unroll
        for (int ks = 0; ks < 2; ks++) {
            uint32_t bh[NT][2], bl[NT][2];
            #pragma unroll
            for (int nt = 0; nt < NT; nt++) {
                uint32_t ba = sb + ((5120 + (wn * (NT * 8) + nt * 8 + brow_t) * PADW
                                     + ks * 8 + bword_t) << 2);
                ldsm_x2(bh[nt][0], bh[nt][1], ba);
                if (EMU == 0) ldsm_x2(bl[nt][0], bl[nt][1], ba + (2560 << 2));
            }
            #pragma unroll
            for (int mt = 0; mt < 2; mt++) {
                uint32_t aa = sb + (((wm * 32 + mt * 16 + arow_t) * PADW
                                     + ks * 8 + aword_t) << 2);
                uint32_t ah0, ah1, ah2, ah3, al0, al1, al2, al3;
                ldsm_x4(ah0, ah1, ah2, ah3, aa);
                ldsm_x4(al0, al1, al2, al3, aa + (2560 << 2));
                #pragma unroll
                for (int nt = 0; nt < NT; nt++) {
                    if (EMU == 0) {
                        mma_bf16(acc[mt][nt], ah0, ah1, ah2, ah3, bh[nt][0], bh[nt][1]);
                        mma_bf16(acc[mt][nt], ah0, ah1, ah2, ah3, bl[nt][0], bl[nt][1]);
                        mma_bf16(acc[mt][nt], al0, al1, al2, al3, bh[nt][0], bh[nt][1]);
                    } else {
                        mma_f16(acc[mt][nt], ah0, ah1, ah2, ah3, bh[nt][0], bh[nt][1]);
                        mma_f16(acc[mt][nt], al0, al1, al2, al3, bh[nt][0], bh[nt][1]);
                    }
                }
            }
        }
        if (kc < 31) cvtstore(dsm + (stage ^ 1) * STG);
        stage ^= 1;
    }

    #pragma unroll
    for (int mt = 0; mt < 2; mt++) {
        #pragma unroll
        for (int nt = 0; nt < NT; nt++) {
            int n = n0 + wn * (NT * 8) + nt * 8 + tq * 2;
            float b0v = __ldg(bias + n), b1v = __ldg(bias + n + 1);
            #pragma unroll
            for (int hf = 0; hf < 2; hf++) {
                int m = m0 + wm * 32 + mt * 16 + lq + hf * 8;
                float v0 = acc[mt][nt][hf * 2 + 0] + b0v;
                float v1 = acc[mt][nt][hf * 2 + 1] + b1v;
                if (PAIR) {
                    int bb = m / S_, srow = m % S_;
                    int h = n >> 6, d = n & 63;
                    size_t idx = (((size_t)bb * H_ + h) * S_ + srow) * DH_ + d;
                    if (EMU == 0) {
                        __nv_bfloat16 h0 = __float2bfloat16(v0);
                        __nv_bfloat16 h1 = __float2bfloat16(v1);
                        __nv_bfloat162 hv; hv.x = h0; hv.y = h1;
                        __nv_bfloat162 lv;
                        lv.x = __float2bfloat16(v0 - __bfloat162float(h0));
                        lv.y = __float2bfloat16(v1 - __bfloat162float(h1));
                        *(__nv_bfloat162*)((__nv_bfloat16*)outHv + idx) = hv;
                        *(__nv_bfloat162*)((__nv_bfloat16*)outLv + idx) = lv;
                    } else {
                        __half h0 = __float2half(v0);
                        __half h1 = __float2half(v1);
                        __half2 hv; hv.x = h0; hv.y = h1;
                        __half2 lv;
                        lv.x = __float2half(v0 - __half2float(h0));
                        lv.y = __float2half(v1 - __half2float(h1));
                        *(__half2*)((__half*)outHv + idx) = hv;
                        *(__half2*)((__half*)outLv + idx) = lv;
                    }
                } else {
                    *(float2*)&outF[(size_t)m * D_ + n] = make_float2(v0, v1);
                }
            }
        }
    }
}

__global__ __launch_bounds__(512, 1)
void gemm_qkv(const float* __restrict__ q, const float* __restrict__ k,
              const float* __restrict__ v, const float* __restrict__ Wk,
              const float* __restrict__ bk, const float* __restrict__ Wv,
              const float* __restrict__ bv)
{
    extern __shared__ __align__(16) uint32_t dsm[];
    int z = blockIdx.z;
    if (z == 2) {
        gemm_body<true, 1, 4>(v, Wv, bv, nullptr, g_vhh, g_vhl,
                              blockIdx.y * 128, blockIdx.x * 128, dsm);
    } else {
        const float* A    = (z == 0) ? q : k;
        __nv_bfloat16* oh = (z == 0) ? g_qhh : g_khh;
        __nv_bfloat16* ol = (z == 0) ? g_qhl : g_khl;
        gemm_body<true, 0, 4>(A, Wk, bk, nullptr, oh, ol,
                              blockIdx.y * 128, blockIdx.x * 128, dsm);
    }
}

// gemm_out: 128x64 tiles -> 512 CTAs (3.46 waves; tail loss 27% -> 13%)
__global__ __launch_bounds__(512, 1)
void gemm_out(const float* __restrict__ A, const float* __restrict__ W,
              const float* __restrict__ bias, float* __restrict__ out)
{
    extern __shared__ __align__(16) uint32_t dsm[];
    gemm_body<false, 1, 2>(A, W, bias, out, nullptr, nullptr,
                           blockIdx.y * 128, blockIdx.x * 64, dsm);
}

// ==================================================================================
// Scores via MMA (bf16x3) + folded dv precompute (tiles t >= 10).
// ==================================================================================
#define PADS 36

__global__ __launch_bounds__(256, 1)
void scores_mma(const float* __restrict__ pdiff)
{
    extern __shared__ __align__(16) uint32_t sm[];
    int z = blockIdx.y;
    int t = blockIdx.x;

    if (t >= 10) {
        // ---- folded dv work: dv[b,i,j] = exp(sigmoid(pdiff)) ----
        int sl = z * 6 + (t - 10);              // 0..767
        const int TOT = B_ * S_ * S_ / 4;       // 524288 float4
        const int PER = (TOT + 767) / 768;      // 683
        int lo = sl * PER;
        int hi = min(lo + PER, TOT);
        for (int i4 = lo + threadIdx.x; i4 < hi; i4 += 256) {
            float4 x = ((const float4*)pdiff)[i4];
            float4 r;
            r.x = __expf(1.f / (1.f + __expf(-x.x)));
            r.y = __expf(1.f / (1.f + __expf(-x.y)));
            r.z = __expf(1.f / (1.f + __expf(-x.z)));
            r.w = __expf(1.f / (1.f + __expf(-x.w)));
            ((float4*)g_dv)[i4] = r;
        }
        return;
    }

    uint32_t* sQh = sm;
    uint32_t* sQl = sm + 4608;
    uint32_t* sKh = sm + 9216;
    uint32_t* sKl = sm + 13824;

    int mi = (t < 1) ? 0 : (t < 3) ? 1 : (t < 6) ? 2 : 3;
    int ni = t - mi * (mi + 1) / 2;
    int m0 = mi * 128, n0 = ni * 128;

    int tid = threadIdx.x, lane = tid & 31, wid = tid >> 5;
    int wm = wid >> 2, wn = wid & 3, lq = lane >> 2, tq = lane & 3;

    uint32_t sbase = smem_u32(sm);
    int sub     = lane >> 3;
    int arow_t  = ((sub & 1) << 3) + (lane & 7);
    int aword_t = (sub >> 1) << 2;
    int brow_t  = lane & 7;
    int bword_t = ((lane >> 3) & 1) << 2;

    const uint32_t* qh = (const uint32_t*)(g_qhh + (size_t)z * S_ * DH_);
    const uint32_t* ql = (const uint32_t*)(g_qhl + (size_t)z * S_ * DH_);
    const uint32_t* kh = (const uint32_t*)(g_khh + (size_t)z * S_ * DH_);
    const uint32_t* kl = (const uint32_t*)(g_khl + (size_t)z * S_ * DH_);

    {
        int row = tid >> 1, hf = tid & 1;
        int gq = (m0 + row) * 32 + hf * 16;
        int gk = (n0 + row) * 32 + hf * 16;
        int so = row * PADS + hf * 16;
        #pragma unroll
        for (int qd = 0; qd < 4; qd++) {
            *(uint4*)(sQh + so + qd * 4) = *(const uint4*)(qh + gq + qd * 4);
            *(uint4*)(sQl + so + qd * 4) = *(const uint4*)(ql + gq + qd * 4);
            *(uint4*)(sKh + so + qd * 4) = *(const uint4*)(kh + gk + qd * 4);
            *(uint4*)(sKl + so + qd * 4) = *(const uint4*)(kl + gk + qd * 4);
        }
    }
    __syncthreads();

    float acc[4][4][4];
    #pragma unroll
    for (int mt = 0; mt < 4; mt++)
        #pragma unroll
        for (int nt = 0; nt < 4; nt++)
            #pragma unroll
            for (int e = 0; e < 4; e++) acc[mt][nt][e] = 0.f;

    #pragma unroll
    for (int ks = 0; ks < 4; ks++) {
        uint32_t bh[4][2], bl[4][2];
        #pragma unroll
        for (int nt = 0; nt < 4; nt++) {
            uint32_t ba = sbase + ((9216 + (wn * 32 + nt * 8 + brow_t) * PADS
                                    + ks * 8 + bword_t) << 2);
            ldsm_x2(bh[nt][0], bh[nt][1], ba);
            ldsm_x2(bl[nt][0], bl[nt][1], ba + (4608 << 2));
        }
        #pragma unroll
        for (int mt = 0; mt < 4; mt++) {
            uint32_t aa = sbase + (((wm * 64 + mt * 16 + arow_t) * PADS
                                    + ks * 8 + aword_t) << 2);
            uint32_t ah0, ah1, ah2, ah3, al0, al1, al2, al3;
            ldsm_x4(ah0, ah1, ah2, ah3, aa);
            ldsm_x4(al0, al1, al2, al3, aa + (4608 << 2));
            #pragma unroll
            for (int nt = 0; nt < 4; nt++) {
                mma_bf16(acc[mt][nt], ah0, ah1, ah2, ah3, bh[nt][0], bh[nt][1]);
                mma_bf16(acc[mt][nt], ah0, ah1, ah2, ah3, bl[nt][0], bl[nt][1]);
                mma_bf16(acc[mt][nt], al0, al1, al2, al3, bh[nt][0], bh[nt][1]);
            }
        }
    }

    float* C = g_sc + (size_t)z * S_ * S_;
    #pragma unroll
    for (int mt = 0; mt < 4; mt++) {
        #pragma unroll
        for (int nt = 0; nt < 4; nt++) {
            int j = n0 + wn * 32 + nt * 8 + tq * 2;
            #pragma unroll
            for (int hf = 0; hf < 2; hf++) {
                int i = m0 + wm * 64 + mt * 16 + lq + hf * 8;
                *(float2*)&C[(size_t)i * S_ + j] =
                    make_float2(acc[mt][nt][hf * 2] * 0.125f,
                                acc[mt][nt][hf * 2 + 1] * 0.125f);
            }
        }
    }
}

// ==================================================================================
// Row kernel (vectorized, fp16 hi/lo P output).
// ==================================================================================
__global__ __launch_bounds__(256)
void row_kernel(const float* __restrict__ gammas)
{
    int warp = threadIdx.x >> 5, lane = threadIdx.x & 31;
    int i = blockIdx.x * 8 + warp;
    int z = blockIdx.y;
    int b = z >> 4, h = z & 15;

    const float* row   = g_sc + ((size_t)z * S_ + i) * S_;
    const float* dvrow = g_dv + ((size_t)b * S_ + i) * S_;

    int nc4 = (i >> 7) + 1;
    float4 scv[4], s2v[4];

    #pragma unroll
    for (int c = 0; c < 4; c++)
        if (c < nc4) scv[c] = *(const float4*)(row + c * 128 + lane * 4);

    float run = 0.f;
    #pragma unroll
    for (int c = 0; c < 4; c++) {
        if (c < nc4) {
            int j0 = c * 128 + lane * 4;
            float p0 = (j0 + 0 <= i) ? __expf(scv[c].x) : 0.f;
            float p1 = (j0 + 1 <= i) ? __expf(scv[c].y) : 0.f;
            float p2 = (j0 + 2 <= i) ? __expf(scv[c].z) : 0.f;
            float p3 = (j0 + 3 <= i) ? __expf(scv[c].w) : 0.f;
            float q1 = p0 + p1;
            float q2 = q1 + p2;
            float q3 = q2 + p3;
            float s = q3;
            #pragma unroll
            for (int d = 1; d < 32; d <<= 1) {
                float tt = __shfl_up_sync(0xFFFFFFFFu, s, d);
                if (lane >= d) s += tt;
            }
            float excl = run + (s - q3);
            s2v[c].x = excl + p0;
            s2v[c].y = excl + q1;
            s2v[c].z = excl + q2;
            s2v[c].w = excl + q3;
            run += __shfl_sync(0xFFFFFFFFu, s, 31);
        }
    }
    float tot  = run;
    float rtot = 1.f / fmaxf(tot, 1e-30f);

    float g = gammas[h];
    float gamma = -log1pf(__expf(g));

    float4 dvv[4];
    #pragma unroll
    for (int c = 0; c < 4; c++)
        if (c < nc4) dvv[c] = *(const float4*)(dvrow + c * 128 + lane * 4);

    float sum2 = 0.f;
    #pragma unroll
    for (int c = 0; c < 4; c++) {
        if (c < nc4) {
            int j0 = c * 128 + lane * 4;
            float e[4];
            float sc[4] = {scv[c].x, scv[c].y, scv[c].z, scv[c].w};
            float cu[4] = {s2v[c].x, s2v[c].y, s2v[c].z, s2v[c].w};
            float dv[4] = {dvv[c].x, dvv[c].y, dvv[c].z, dvv[c].w};
            #pragma unroll
            for (int e4 = 0; e4 < 4; e4++) {
                int j = j0 + e4;
                float rem  = fmaxf(tot - cu[e4], 0.f) * rtot;
                float pos  = (float)(i - j);
                float dist = sqrtf(fmaxf(rem * pos, 0.f));
                float eff  = fmaxf(__expf(dist * gamma * dv[e4]), 1e-5f);
                float s2 = sc[e4] * eff;
                e[e4] = (j <= i) ? __expf(s2) : 0.f;
                sum2 += e[e4];
            }
            s2v[c] = make_float4(e[0], e[1], e[2], e[3]);
        }
    }
    #pragma unroll
    for (int o = 16; o > 0; o >>= 1) sum2 += __shfl_xor_sync(0xFFFFFFFFu, sum2, o);

    float rs = (i == 0) ? 0.f : 1.f / sum2;

    __half* ph = g_phi + ((size_t)z * S_ + i) * S_;
    __half* pl = g_plo + ((size_t)z * S_ + i) * S_;
    #pragma unroll
    for (int c = 0; c < 4; c++) {
        if (c < nc4) {
            int j0 = c * 128 + lane * 4;
            float p0 = s2v[c].x * rs, p1 = s2v[c].y * rs;
            float p2 = s2v[c].z * rs, p3 = s2v[c].w * rs;
            uint32_t h01 = pack_f16(p0, p1), h23 = pack_f16(p2, p3);
            __half2 hh01 = *(__half2*)&h01;
            __half2 hh23 = *(__half2*)&h23;
            uint32_t l01 = pack_f16(p0 - __half2float(hh01.x),
                                    p1 - __half2float(hh01.y));
            uint32_t l23 = pack_f16(p2 - __half2float(hh23.x),
                                    p3 - __half2float(hh23.y));
            *(uint2*)(ph + j0) = make_uint2(h01, h23);
            *(uint2*)(pl + j0) = make_uint2(l01, l23);
        }
    }
}

// ==================================================================================
// PV via MMA, fp16 2-pass: out = (Ph+Pl)*Vh. 128(M) x 64(N).
// ==================================================================================
__global__ __launch_bounds__(256, 1)
void pv_mma()
{
    extern __shared__ __align__(16) uint32_t sm[];
    uint32_t* sPh = sm;
    uint32_t* sPl = sm + 4608;
    uint32_t* sVh = sm + 9216;
    __half* sVh16 = (__half*)sVh;

    int z  = blockIdx.y;
    int b  = z >> 4, h = z & 15;
    int m0 = (3 - (int)blockIdx.x) * 128;

    int tid = threadIdx.x, lane = tid & 31, wid = tid >> 5;
    int wm = wid >> 2, wn = wid & 3, lq = lane >> 2, tq = lane & 3;

    const uint32_t* pwh = (const uint32_t*)(g_phi + (size_t)z * S_ * S_);
    const uint32_t* pwl = (const uint32_t*)(g_plo + (size_t)z * S_ * S_);
    const uint32_t* vwh = (const uint32_t*)(g_vhh + (size_t)z * S_ * DH_);

    float acc[4][2][4];
    #pragma unroll
    for (int mt = 0; mt < 4; mt++)
        #pragma unroll
        for (int nt = 0; nt < 2; nt++)
            #pragma unroll
            for (int e = 0; e < 4; e++) acc[mt][nt][e] = 0.f;

    int nchunks = m0 / 64 + 2;

    for (int c = 0; c < nchunks; c++) {
        int k0 = c * 64;
        {
            int row = tid >> 1, hf = tid & 1;
            int gofs = (m0 + row) * 256 + k0 / 2 + hf * 16;
            int so = row * PADS + hf * 16;
            #pragma unroll
            for (int qd = 0; qd < 4; qd++) {
                *(uint4*)(sPh + so + qd * 4) = *(const uint4*)(pwh + gofs + qd * 4);
                *(uint4*)(sPl + so + qd * 4) = *(const uint4*)(pwl + gofs + qd * 4);
            }
        }
        {
            int r  = tid >> 2;
            int w0 = (tid & 3) * 8;
            #pragma unroll
            for (int qd = 0; qd < 2; qd++) {
                uint4 vv = *(const uint4*)(vwh + (k0 + r) * 32 + w0 + qd * 4);
                uint32_t wv[4] = {vv.x, vv.y, vv.z, vv.w};
                #pragma unroll
                for (int q2 = 0; q2 < 4; q2++) {
                    int d0 = (w0 + qd * 4 + q2) * 2;
                    __half2 pr = *(__half2*)&wv[q2];
                    sVh16[d0 * 72 + r]       = pr.x;
                    sVh16[(d0 + 1) * 72 + r] = pr.y;
                }
            }
        }
        __syncthreads();

        #pragma unroll
        for (int ks = 0; ks < 4; ks++) {
            int kofs = ks * 8 + tq;
            uint32_t bh[2][2];
            #pragma unroll
            for (int nt = 0; nt < 2; nt++) {
                int bi = (wn * 16 + nt * 8 + lq) * PADS + kofs;
                bh[nt][0] = sVh[bi]; bh[nt][1] = sVh[bi + 4];
            }
            #pragma unroll
            for (int mt = 0; mt < 4; mt++) {
                int ai = (wm * 64 + mt * 16 + lq) * PADS + kofs;
                uint32_t ah0 = sPh[ai],     ah1 = sPh[ai + 8 * PADS];
                uint32_t ah2 = sPh[ai + 4], ah3 = sPh[ai + 8 * PADS + 4];
                uint32_t al0 = sPl[ai],     al1 = sPl[ai + 8 * PADS];
                uint32_t al2 = sPl[ai + 4], al3 = sPl[ai + 8 * PADS + 4];
                #pragma unroll
                for (int nt = 0; nt < 2; nt++) {
                    mma_f16(acc[mt][nt], ah0, ah1, ah2, ah3, bh[nt][0], bh[nt][1]);
                    mma_f16(acc[mt][nt], al0, al1, al2, al3, bh[nt][0], bh[nt][1]);
                }
            }
        }
        __syncthreads();
    }

    #pragma unroll
    for (int mt = 0; mt < 4; mt++) {
        #pragma unroll
        for (int nt = 0; nt < 2; nt++) {
            int d = wn * 16 + nt * 8 + tq * 2;
            #pragma unroll
            for (int hf = 0; hf < 2; hf++) {
                int i = m0 + wm * 64 + mt * 16 + lq + hf * 8;
                *(float2*)&g_att[((size_t)b * S_ + i) * D_ + h * DH_ + d] =
                    make_float2(acc[mt][nt][hf * 2], acc[mt][nt][hf * 2 + 1]);
            }
        }
    }
}

// ==================================================================================
extern "C" void kernel_launch(void* const* d_in, const int* in_sizes, int n_in,
                              void* d_out, int out_size)
{
    const float* q      = (const float*)d_in[0];
    const float* k      = (const float*)d_in[1];
    const float* v      = (const float*)d_in[2];
    const float* pdiff  = (const float*)d_in[3];
    const float* Wk     = (const float*)d_in[4];
    const float* bk     = (const float*)d_in[5];
    const float* Wv     = (const float*)d_in[6];
    const float* bv     = (const float*)d_in[7];
    const float* Wo     = (const float*)d_in[8];
    const float* bo     = (const float*)d_in[9];
    const float* gammas = (const float*)d_in[10];
    float* out = (float*)d_out;

    float* att;
    cudaGetSymbolAddress((void**)&att, g_att);

    cudaFuncSetAttribute(gemm_qkv,   cudaFuncAttributeMaxDynamicSharedMemorySize, 81920);
    cudaFuncSetAttribute(gemm_out,   cudaFuncAttributeMaxDynamicSharedMemorySize, 81920);
    cudaFuncSetAttribute(scores_mma, cudaFuncAttributeMaxDynamicSharedMemorySize, 73728);
    cudaFuncSetAttribute(pv_mma,     cudaFuncAttributeMaxDynamicSharedMemorySize, 46080);

    gemm_qkv<<<dim3(8, 32, 3), 512, 81920>>>(q, k, v, Wk, bk, Wv, bv);

    scores_mma<<<dim3(16, BH_), 256, 73728>>>(pdiff);

    row_kernel<<<dim3(S_ / 8, BH_), 256>>>(gammas);

    pv_mma<<<dim3(4, BH_), 256, 46080>>>();

    gemm_out<<<dim3(16, 32), 512, 81920>>>(att, Wo, bo, out);
}

// round 15
// speedup vs baseline: 1.0497x; 1.0497x over previous
#include <cuda_runtime.h>
#include <cuda_bf16.h>
#include <cuda_fp16.h>
#include <math.h>
#include <stdint.h>

#define B_  8
#define S_  512
#define D_  1024
#define H_  16
#define DH_ 64
#define BH_ 128

// ---------------- scratch (device globals; no runtime allocation) ----------------
__device__ float g_sc [(size_t)BH_*S_*S_];            // fp32 scores -> fp32 probs (in-place)
__device__ float g_att[(size_t)B_*S_*D_];             // attention out, concat [B,S,D]
__device__ float g_dv [(size_t)B_*S_*S_];             // exp(sigmoid(pdiff))
__device__ __nv_bfloat16 g_qhh[(size_t)BH_*S_*DH_], g_qhl[(size_t)BH_*S_*DH_];
__device__ __nv_bfloat16 g_khh[(size_t)BH_*S_*DH_], g_khl[(size_t)BH_*S_*DH_];
__device__ __half        g_vhh[(size_t)BH_*S_*DH_], g_vhl[(size_t)BH_*S_*DH_];   // fp16

// ======================= warp-level MMA + ldmatrix ================================
__device__ __forceinline__ void mma_bf16(float* c, uint32_t a0, uint32_t a1,
                                         uint32_t a2, uint32_t a3,
                                         uint32_t b0, uint32_t b1) {
    asm volatile(
        "mma.sync.aligned.m16n8k16.row.col.f32.bf16.bf16.f32 "
        "{%0,%1,%2,%3}, {%4,%5,%6,%7}, {%8,%9}, {%0,%1,%2,%3};"
        : "+f"(c[0]), "+f"(c[1]), "+f"(c[2]), "+f"(c[3])
        : "r"(a0), "r"(a1), "r"(a2), "r"(a3), "r"(b0), "r"(b1));
}
__device__ __forceinline__ void mma_f16(float* c, uint32_t a0, uint32_t a1,
                                        uint32_t a2, uint32_t a3,
                                        uint32_t b0, uint32_t b1) {
    asm volatile(
        "mma.sync.aligned.m16n8k16.row.col.f32.f16.f16.f32 "
        "{%0,%1,%2,%3}, {%4,%5,%6,%7}, {%8,%9}, {%0,%1,%2,%3};"
        : "+f"(c[0]), "+f"(c[1]), "+f"(c[2]), "+f"(c[3])
        : "r"(a0), "r"(a1), "r"(a2), "r"(a3), "r"(b0), "r"(b1));
}
__device__ __forceinline__ uint32_t smem_u32(const void* p) {
    uint32_t a;
    asm("{ .reg .u64 t; cvta.to.shared.u64 t, %1; cvt.u32.u64 %0, t; }" : "=r"(a) : "l"(p));
    return a;
}
__device__ __forceinline__ void ldsm_x4(uint32_t& r0, uint32_t& r1, uint32_t& r2,
                                        uint32_t& r3, uint32_t a) {
    asm volatile("ldmatrix.sync.aligned.m8n8.x4.shared.b16 {%0,%1,%2,%3}, [%4];"
                 : "=r"(r0), "=r"(r1), "=r"(r2), "=r"(r3) : "r"(a));
}
__device__ __forceinline__ void ldsm_x2(uint32_t& r0, uint32_t& r1, uint32_t a) {
    asm volatile("ldmatrix.sync.aligned.m8n8.x2.shared.b16 {%0,%1}, [%2];"
                 : "=r"(r0), "=r"(r1) : "r"(a));
}
__device__ __forceinline__ uint32_t pack_bf16(float x, float y) {
    __nv_bfloat162 t = __floats2bfloat162_rn(x, y);
    return *(uint32_t*)&t;
}
__device__ __forceinline__ uint32_t pack_f16(float x, float y) {
    __half2 t = __floats2half2_rn(x, y);
    return *(uint32_t*)&t;
}
__device__ __forceinline__ void split4(float4 v, uint32_t& h0, uint32_t& h1,
                                       uint32_t& l0, uint32_t& l1) {
    h0 = pack_bf16(v.x, v.y);
    h1 = pack_bf16(v.z, v.w);
    __nv_bfloat162 hh0 = *(__nv_bfloat162*)&h0;
    __nv_bfloat162 hh1 = *(__nv_bfloat162*)&h1;
    l0 = pack_bf16(v.x - __bfloat162float(hh0.x), v.y - __bfloat162float(hh0.y));
    l1 = pack_bf16(v.z - __bfloat162float(hh1.x), v.w - __bfloat162float(hh1.y));
}
__device__ __forceinline__ void split4h(float4 v, uint32_t& h0, uint32_t& h1,
                                        uint32_t& l0, uint32_t& l1) {
    __half2 a = __floats2half2_rn(v.x, v.y);
    __half2 b = __floats2half2_rn(v.z, v.w);
    h0 = *(uint32_t*)&a;
    h1 = *(uint32_t*)&b;
    __half2 la = __floats2half2_rn(v.x - __half2float(__low2half(a)),
                                   v.y - __half2float(__high2half(a)));
    __half2 lb = __floats2half2_rn(v.z - __half2float(__low2half(b)),
                                   v.w - __half2float(__high2half(b)));
    l0 = *(uint32_t*)&la;
    l1 = *(uint32_t*)&lb;
}

// ==================================================================================
// Double-buffered emulated-fp32 GEMM (R13 config), 512 threads, LDSM fragments.
// EMU=0: bf16 3-pass; EMU=1: fp16 2-pass.  Block 128x128, BK=32, warp grid 4x4.
// ==================================================================================
#define PADW 20
#define STG  10240

template<bool PAIR, int EMU>
__device__ __forceinline__ void gemm_body(const float* __restrict__ A,
                                          const float* __restrict__ W,
                                          const float* __restrict__ bias,
                                          float* outF, void* outHv, void* outLv,
                                          int m0, int n0, uint32_t* dsm)
{
    int tid = threadIdx.x, lane = tid & 31, wid = tid >> 5;
    int wm = wid >> 2, wn = wid & 3;
    int lq = lane >> 2, tq = lane & 3;

    uint32_t sbase = smem_u32(dsm);
    int sub     = lane >> 3;
    int arow_t  = ((sub & 1) << 3) + (lane & 7);
    int aword_t = (sub >> 1) << 2;
    int brow_t  = lane & 7;
    int bword_t = ((lane >> 3) & 1) << 2;

    float acc[2][4][4];
    #pragma unroll
    for (int mt = 0; mt < 2; mt++)
        #pragma unroll
        for (int nt = 0; nt < 4; nt++)
            #pragma unroll
            for (int e = 0; e < 4; e++) acc[mt][nt][e] = 0.f;

    int rowr[2], cqr[2], wofs[2];
    #pragma unroll
    for (int r = 0; r < 2; r++) {
        int g = tid + r * 512;
        rowr[r] = g >> 3;
        cqr[r]  = g & 7;
        wofs[r] = rowr[r] * PADW + cqr[r] * 2;
    }

    float4 va[2], vb[2];
    auto fetch = [&](int kc) {
        int k0 = kc * 32;
        #pragma unroll
        for (int r = 0; r < 2; r++) {
            va[r] = *(const float4*)(A + (size_t)(m0 + rowr[r]) * D_ + k0 + cqr[r] * 4);
            vb[r] = *(const float4*)(W + (size_t)(n0 + rowr[r]) * D_ + k0 + cqr[r] * 4);
        }
    };
    auto cvtstore = [&](uint32_t* base) {
        #pragma unroll
        for (int r = 0; r < 2; r++) {
            uint32_t h0, h1, l0, l1;
            if (EMU == 0) split4 (va[r], h0, h1, l0, l1);
            else          split4h(va[r], h0, h1, l0, l1);
            base[wofs[r]]        = h0; base[wofs[r] + 1]        = h1;
            base[2560 + wofs[r]] = l0; base[2560 + wofs[r] + 1] = l1;
            if (EMU == 0) split4 (vb[r], h0, h1, l0, l1);
            else          split4h(vb[r], h0, h1, l0, l1);
            base[5120 + wofs[r]] = h0; base[5120 + wofs[r] + 1] = h1;
            if (EMU == 0) {
                base[7680 + wofs[r]] = l0; base[7680 + wofs[r] + 1] = l1;
            }
        }
    };

    fetch(0);
    cvtstore(dsm);
    int stage = 0;

    for (int kc = 0; kc < 32; kc++) {
        __syncthreads();
        if (kc < 31) fetch(kc + 1);
        uint32_t sb = sbase + stage * (STG * 4);
        #pragma unroll
        for (int ks = 0; ks < 2; ks++) {
            uint32_t bh[4][2], bl[4][2];
            #pragma unroll
            for (int nt = 0; nt < 4; nt++) {
                uint32_t ba = sb + ((5120 + (wn * 32 + nt * 8 + brow_t) * PADW
                                     + ks * 8 + bword_t) << 2);
                ldsm_x2(bh[nt][0], bh[nt][1], ba);
                if (EMU == 0) ldsm_x2(bl[nt][0], bl[nt][1], ba + (2560 << 2));
            }
            #pragma unroll
            for (int mt = 0; mt < 2; mt++) {
                uint32_t aa = sb + (((wm * 32 + mt * 16 + arow_t) * PADW
                                     + ks * 8 + aword_t) << 2);
                uint32_t ah0, ah1, ah2, ah3, al0, al1, al2, al3;
                ldsm_x4(ah0, ah1, ah2, ah3, aa);
                ldsm_x4(al0, al1, al2, al3, aa + (2560 << 2));
                #pragma unroll
                for (int nt = 0; nt < 4; nt++) {
                    if (EMU == 0) {
                        mma_bf16(acc[mt][nt], ah0, ah1, ah2, ah3, bh[nt][0], bh[nt][1]);
                        mma_bf16(acc[mt][nt], ah0, ah1, ah2, ah3, bl[nt][0], bl[nt][1]);
                        mma_bf16(acc[mt][nt], al0, al1, al2, al3, bh[nt][0], bh[nt][1]);
                    } else {
                        mma_f16(acc[mt][nt], ah0, ah1, ah2, ah3, bh[nt][0], bh[nt][1]);
                        mma_f16(acc[mt][nt], al0, al1, al2, al3, bh[nt][0], bh[nt][1]);
                    }
                }
            }
        }
        if (kc < 31) cvtstore(dsm + (stage ^ 1) * STG);
        stage ^= 1;
    }

    #pragma unroll
    for (int mt = 0; mt < 2; mt++) {
        #pragma unroll
        for (int nt = 0; nt < 4; nt++) {
            int n = n0 + wn * 32 + nt * 8 + tq * 2;
            float b0v = __ldg(bias + n), b1v = __ldg(bias + n + 1);
            #pragma unroll
            for (int hf = 0; hf < 2; hf++) {
                int m = m0 + wm * 32 + mt * 16 + lq + hf * 8;
                float v0 = acc[mt][nt][hf * 2 + 0] + b0v;
                float v1 = acc[mt][nt][hf * 2 + 1] + b1v;
                if (PAIR) {
                    int bb = m / S_, srow = m % S_;
                    int h = n >> 6, d = n & 63;
                    size_t idx = (((size_t)bb * H_ + h) * S_ + srow) * DH_ + d;
                    if (EMU == 0) {
                        __nv_bfloat16 h0 = __float2bfloat16(v0);
                        __nv_bfloat16 h1 = __float2bfloat16(v1);
                        __nv_bfloat162 hv; hv.x = h0; hv.y = h1;
                        __nv_bfloat162 lv;
                        lv.x = __float2bfloat16(v0 - __bfloat162float(h0));
                        lv.y = __float2bfloat16(v1 - __bfloat162float(h1));
                        *(__nv_bfloat162*)((__nv_bfloat16*)outHv + idx) = hv;
                        *(__nv_bfloat162*)((__nv_bfloat16*)outLv + idx) = lv;
                    } else {
                        __half h0 = __float2half(v0);
                        __half h1 = __float2half(v1);
                        __half2 hv; hv.x = h0; hv.y = h1;
                        __half2 lv;
                        lv.x = __float2half(v0 - __half2float(h0));
                        lv.y = __float2half(v1 - __half2float(h1));
                        *(__half2*)((__half*)outHv + idx) = hv;
                        *(__half2*)((__half*)outLv + idx) = lv;
                    }
                } else {
                    *(float2*)&outF[(size_t)m * D_ + n] = make_float2(v0, v1);
                }
            }
        }
    }
}

__global__ __launch_bounds__(512, 1)
void gemm_qkv(const float* __restrict__ q, const float* __restrict__ k,
              const float* __restrict__ v, const float* __restrict__ Wk,
              const float* __restrict__ bk, const float* __restrict__ Wv,
              const float* __restrict__ bv)
{
    extern __shared__ __align__(16) uint32_t dsm[];
    int z = blockIdx.z;
    if (z == 2) {
        gemm_body<true, 1>(v, Wv, bv, nullptr, g_vhh, g_vhl,
                           blockIdx.y * 128, blockIdx.x * 128, dsm);
    } else {
        const float* A    = (z == 0) ? q : k;
        __nv_bfloat16* oh = (z == 0) ? g_qhh : g_khh;
        __nv_bfloat16* ol = (z == 0) ? g_qhl : g_khl;
        gemm_body<true, 0>(A, Wk, bk, nullptr, oh, ol,
                           blockIdx.y * 128, blockIdx.x * 128, dsm);
    }
}

__global__ __launch_bounds__(512, 1)
void gemm_out(const float* __restrict__ A, const float* __restrict__ W,
              const float* __restrict__ bias, float* __restrict__ out)
{
    extern __shared__ __align__(16) uint32_t dsm[];
    gemm_body<false, 1>(A, W, bias, out, nullptr, nullptr,
                        blockIdx.y * 128, blockIdx.x * 128, dsm);
}

// ==================================================================================
// Scores via MMA (bf16x3), R13 config (grid 10 x 128).
// ==================================================================================
#define PADS 36

__global__ __launch_bounds__(256, 1)
void scores_mma()
{
    extern __shared__ __align__(16) uint32_t sm[];
    uint32_t* sQh = sm;
    uint32_t* sQl = sm + 4608;
    uint32_t* sKh = sm + 9216;
    uint32_t* sKl = sm + 13824;

    int z = blockIdx.y;
    int t = blockIdx.x;
    int mi = (t < 1) ? 0 : (t < 3) ? 1 : (t < 6) ? 2 : 3;
    int ni = t - mi * (mi + 1) / 2;
    int m0 = mi * 128, n0 = ni * 128;

    int tid = threadIdx.x, lane = tid & 31, wid = tid >> 5;
    int wm = wid >> 2, wn = wid & 3, lq = lane >> 2, tq = lane & 3;

    uint32_t sbase = smem_u32(sm);
    int sub     = lane >> 3;
    int arow_t  = ((sub & 1) << 3) + (lane & 7);
    int aword_t = (sub >> 1) << 2;
    int brow_t  = lane & 7;
    int bword_t = ((lane >> 3) & 1) << 2;

    const uint32_t* qh = (const uint32_t*)(g_qhh + (size_t)z * S_ * DH_);
    const uint32_t* ql = (const uint32_t*)(g_qhl + (size_t)z * S_ * DH_);
    const uint32_t* kh = (const uint32_t*)(g_khh + (size_t)z * S_ * DH_);
    const uint32_t* kl = (const uint32_t*)(g_khl + (size_t)z * S_ * DH_);

    {
        int row = tid >> 1, hf = tid & 1;
        int gq = (m0 + row) * 32 + hf * 16;
        int gk = (n0 + row) * 32 + hf * 16;
        int so = row * PADS + hf * 16;
        #pragma unroll
        for (int qd = 0; qd < 4; qd++) {
            *(uint4*)(sQh + so + qd * 4) = *(const uint4*)(qh + gq + qd * 4);
            *(uint4*)(sQl + so + qd * 4) = *(const uint4*)(ql + gq + qd * 4);
            *(uint4*)(sKh + so + qd * 4) = *(const uint4*)(kh + gk + qd * 4);
            *(uint4*)(sKl + so + qd * 4) = *(const uint4*)(kl + gk + qd * 4);
        }
    }
    __syncthreads();

    float acc[4][4][4];
    #pragma unroll
    for (int mt = 0; mt < 4; mt++)
        #pragma unroll
        for (int nt = 0; nt < 4; nt++)
            #pragma unroll
            for (int e = 0; e < 4; e++) acc[mt][nt][e] = 0.f;

    #pragma unroll
    for (int ks = 0; ks < 4; ks++) {
        uint32_t bh[4][2], bl[4][2];
        #pragma unroll
        for (int nt = 0; nt < 4; nt++) {
            uint32_t ba = sbase + ((9216 + (wn * 32 + nt * 8 + brow_t) * PADS
                                    + ks * 8 + bword_t) << 2);
            ldsm_x2(bh[nt][0], bh[nt][1], ba);
            ldsm_x2(bl[nt][0], bl[nt][1], ba + (4608 << 2));
        }
        #pragma unroll
        for (int mt = 0; mt < 4; mt++) {
            uint32_t aa = sbase + (((wm * 64 + mt * 16 + arow_t) * PADS
                                    + ks * 8 + aword_t) << 2);
            uint32_t ah0, ah1, ah2, ah3, al0, al1, al2, al3;
            ldsm_x4(ah0, ah1, ah2, ah3, aa);
            ldsm_x4(al0, al1, al2, al3, aa + (4608 << 2));
            #pragma unroll
            for (int nt = 0; nt < 4; nt++) {
                mma_bf16(acc[mt][nt], ah0, ah1, ah2, ah3, bh[nt][0], bh[nt][1]);
                mma_bf16(acc[mt][nt], ah0, ah1, ah2, ah3, bl[nt][0], bl[nt][1]);
                mma_bf16(acc[mt][nt], al0, al1, al2, al3, bh[nt][0], bh[nt][1]);
            }
        }
    }

    float* C = g_sc + (size_t)z * S_ * S_;
    #pragma unroll
    for (int mt = 0; mt < 4; mt++) {
        #pragma unroll
        for (int nt = 0; nt < 4; nt++) {
            int j = n0 + wn * 32 + nt * 8 + tq * 2;
            #pragma unroll
            for (int hf = 0; hf < 2; hf++) {
                int i = m0 + wm * 64 + mt * 16 + lq + hf * 8;
                *(float2*)&C[(size_t)i * S_ + j] =
                    make_float2(acc[mt][nt][hf * 2] * 0.125f,
                                acc[mt][nt][hf * 2 + 1] * 0.125f);
            }
        }
    }
}

// ==================================================================================
// dv precompute (standalone again)
// ==================================================================================
__global__ __launch_bounds__(256)
void dv_kernel(const float* __restrict__ pdiff)
{
    size_t idx = (size_t)blockIdx.x * 256 + threadIdx.x;
    float x = pdiff[idx];
    float sig = 1.f / (1.f + __expf(-x));
    g_dv[idx] = __expf(sig);
}

// ==================================================================================
// Row kernel (vectorized). Writes normalized P back IN-PLACE into g_sc as fp32.
// ==================================================================================
__global__ __launch_bounds__(256)
void row_kernel(const float* __restrict__ gammas)
{
    int warp = threadIdx.x >> 5, lane = threadIdx.x & 31;
    int i = blockIdx.x * 8 + warp;
    int z = blockIdx.y;
    int b = z >> 4, h = z & 15;

    float* row         = g_sc + ((size_t)z * S_ + i) * S_;
    const float* dvrow = g_dv + ((size_t)b * S_ + i) * S_;

    int nc4 = (i >> 7) + 1;
    float4 scv[4], s2v[4];

    #pragma unroll
    for (int c = 0; c < 4; c++)
        if (c < nc4) scv[c] = *(const float4*)(row + c * 128 + lane * 4);

    float run = 0.f;
    #pragma unroll
    for (int c = 0; c < 4; c++) {
        if (c < nc4) {
            int j0 = c * 128 + lane * 4;
            float p0 = (j0 + 0 <= i) ? __expf(scv[c].x) : 0.f;
            float p1 = (j0 + 1 <= i) ? __expf(scv[c].y) : 0.f;
            float p2 = (j0 + 2 <= i) ? __expf(scv[c].z) : 0.f;
            float p3 = (j0 + 3 <= i) ? __expf(scv[c].w) : 0.f;
            float q1 = p0 + p1;
            float q2 = q1 + p2;
            float q3 = q2 + p3;
            float s = q3;
            #pragma unroll
            for (int d = 1; d < 32; d <<= 1) {
                float tt = __shfl_up_sync(0xFFFFFFFFu, s, d);
                if (lane >= d) s += tt;
            }
            float excl = run + (s - q3);
            s2v[c].x = excl + p0;
            s2v[c].y = excl + q1;
            s2v[c].z = excl + q2;
            s2v[c].w = excl + q3;
            run += __shfl_sync(0xFFFFFFFFu, s, 31);
        }
    }
    float tot  = run;
    float rtot = 1.f / fmaxf(tot, 1e-30f);

    float g = gammas[h];
    float gamma = -log1pf(__expf(g));

    float4 dvv[4];
    #pragma unroll
    for (int c = 0; c < 4; c++)
        if (c < nc4) dvv[c] = *(const float4*)(dvrow + c * 128 + lane * 4);

    float sum2 = 0.f;
    #pragma unroll
    for (int c = 0; c < 4; c++) {
        if (c < nc4) {
            int j0 = c * 128 + lane * 4;
            float e[4];
            float sc[4] = {scv[c].x, scv[c].y, scv[c].z, scv[c].w};
            float cu[4] = {s2v[c].x, s2v[c].y, s2v[c].z, s2v[c].w};
            float dv[4] = {dvv[c].x, dvv[c].y, dvv[c].z, dvv[c].w};
            #pragma unroll
            for (int e4 = 0; e4 < 4; e4++) {
                int j = j0 + e4;
                float rem  = fmaxf(tot - cu[e4], 0.f) * rtot;
                float pos  = (float)(i - j);
                float dist = sqrtf(fmaxf(rem * pos, 0.f));
                float eff  = fmaxf(__expf(dist * gamma * dv[e4]), 1e-5f);
                float s2 = sc[e4] * eff;
                e[e4] = (j <= i) ? __expf(s2) : 0.f;
                sum2 += e[e4];
            }
            s2v[c] = make_float4(e[0], e[1], e[2], e[3]);
        }
    }
    #pragma unroll
    for (int o = 16; o > 0; o >>= 1) sum2 += __shfl_xor_sync(0xFFFFFFFFu, sum2, o);

    float rs = (i == 0) ? 0.f : 1.f / sum2;

    // write fp32 normalized probs in-place; zero-pad to 128-col boundary
    #pragma unroll
    for (int c = 0; c < 4; c++) {
        if (c < nc4) {
            int j0 = c * 128 + lane * 4;
            *(float4*)(row + j0) = make_float4(s2v[c].x * rs, s2v[c].y * rs,
                                               s2v[c].z * rs, s2v[c].w * rs);
        }
    }
}

// ==================================================================================
// PV via MMA, fp16 2-pass, OCCUPANCY 2. Reads fp32 P from g_sc; splits to
// fp16 hi/lo during SMEM staging (spare issue slots). 128(M) x 64(N).
// ==================================================================================
__global__ __launch_bounds__(256, 2)
void pv_mma()
{
    extern __shared__ __align__(16) uint32_t sm[];
    uint32_t* sPh = sm;
    uint32_t* sPl = sm + 4608;
    uint32_t* sVh = sm + 9216;
    __half* sVh16 = (__half*)sVh;

    int z  = blockIdx.y;
    int b  = z >> 4, h = z & 15;
    int m0 = (3 - (int)blockIdx.x) * 128;

    int tid = threadIdx.x, lane = tid & 31, wid = tid >> 5;
    int wm = wid >> 2, wn = wid & 3, lq = lane >> 2, tq = lane & 3;

    const float*    psrc = g_sc + (size_t)z * S_ * S_;
    const uint32_t* vwh  = (const uint32_t*)(g_vhh + (size_t)z * S_ * DH_);

    float acc[4][2][4];
    #pragma unroll
    for (int mt = 0; mt < 4; mt++)
        #pragma unroll
        for (int nt = 0; nt < 2; nt++)
            #pragma unroll
            for (int e = 0; e < 4; e++) acc[mt][nt][e] = 0.f;

    int nchunks = m0 / 64 + 2;

    for (int c = 0; c < nchunks; c++) {
        int k0 = c * 64;
        {
            // load fp32 P chunk (128 rows x 64 cols), split to fp16 hi/lo in SMEM
            int row = tid >> 1, hf = tid & 1;       // hf selects 32-col half
            const float* src = psrc + (size_t)(m0 + row) * S_ + k0 + hf * 32;
            int so = row * PADS + hf * 16;          // 16 words = 32 halves
            #pragma unroll
            for (int qd = 0; qd < 8; qd++) {
                float4 v = *(const float4*)(src + qd * 4);
                uint32_t h0, h1, l0, l1;
                split4h(v, h0, h1, l0, l1);
                sPh[so + qd * 2] = h0; sPh[so + qd * 2 + 1] = h1;
                sPl[so + qd * 2] = l0; sPl[so + qd * 2 + 1] = l1;
            }
        }
        {
            int r  = tid >> 2;
            int w0 = (tid & 3) * 8;
            #pragma unroll
            for (int qd = 0; qd < 2; qd++) {
                uint4 vv = *(const uint4*)(vwh + (k0 + r) * 32 + w0 + qd * 4);
                uint32_t wv[4] = {vv.x, vv.y, vv.z, vv.w};
                #pragma unroll
                for (int q2 = 0; q2 < 4; q2++) {
                    int d0 = (w0 + qd * 4 + q2) * 2;
                    __half2 pr = *(__half2*)&wv[q2];
                    sVh16[d0 * 72 + r]       = pr.x;
                    sVh16[(d0 + 1) * 72 + r] = pr.y;
                }
            }
        }
        __syncthreads();

        #pragma unroll
        for (int ks = 0; ks < 4; ks++) {
            int kofs = ks * 8 + tq;
            uint32_t bh[2][2];
            #pragma unroll
            for (int nt = 0; nt < 2; nt++) {
                int bi = (wn * 16 + nt * 8 + lq) * PADS + kofs;
                bh[nt][0] = sVh[bi]; bh[nt][1] = sVh[bi + 4];
            }
            #pragma unroll
            for (int mt = 0; mt < 4; mt++) {
                int ai = (wm * 64 + mt * 16 + lq) * PADS + kofs;
                uint32_t ah0 = sPh[ai],     ah1 = sPh[ai + 8 * PADS];
                uint32_t ah2 = sPh[ai + 4], ah3 = sPh[ai + 8 * PADS + 4];
                uint32_t al0 = sPl[ai],     al1 = sPl[ai + 8 * PADS];
                uint32_t al2 = sPl[ai + 4], al3 = sPl[ai + 8 * PADS + 4];
                #pragma unroll
                for (int nt = 0; nt < 2; nt++) {
                    mma_f16(acc[mt][nt], ah0, ah1, ah2, ah3, bh[nt][0], bh[nt][1]);
                    mma_f16(acc[mt][nt], al0, al1, al2, al3, bh[nt][0], bh[nt][1]);
                }
            }
        }
        __syncthreads();
    }

    #pragma unroll
    for (int mt = 0; mt < 4; mt++) {
        #pragma unroll
        for (int nt = 0; nt < 2; nt++) {
            int d = wn * 16 + nt * 8 + tq * 2;
            #pragma unroll
            for (int hf = 0; hf < 2; hf++) {
                int i = m0 + wm * 64 + mt * 16 + lq + hf * 8;
                *(float2*)&g_att[((size_t)b * S_ + i) * D_ + h * DH_ + d] =
                    make_float2(acc[mt][nt][hf * 2], acc[mt][nt][hf * 2 + 1]);
            }
        }
    }
}

// ==================================================================================
extern "C" void kernel_launch(void* const* d_in, const int* in_sizes, int n_in,
                              void* d_out, int out_size)
{
    const float* q      = (const float*)d_in[0];
    const float* k      = (const float*)d_in[1];
    const float* v      = (const float*)d_in[2];
    const float* pdiff  = (const float*)d_in[3];
    const float* Wk     = (const float*)d_in[4];
    const float* bk     = (const float*)d_in[5];
    const float* Wv     = (const float*)d_in[6];
    const float* bv     = (const float*)d_in[7];
    const float* Wo     = (const float*)d_in[8];
    const float* bo     = (const float*)d_in[9];
    const float* gammas = (const float*)d_in[10];
    float* out = (float*)d_out;

    float* att;
    cudaGetSymbolAddress((void**)&att, g_att);

    cudaFuncSetAttribute(gemm_qkv,   cudaFuncAttributeMaxDynamicSharedMemorySize, 81920);
    cudaFuncSetAttribute(gemm_out,   cudaFuncAttributeMaxDynamicSharedMemorySize, 81920);
    cudaFuncSetAttribute(scores_mma, cudaFuncAttributeMaxDynamicSharedMemorySize, 73728);
    cudaFuncSetAttribute(pv_mma,     cudaFuncAttributeMaxDynamicSharedMemorySize, 46080);

    gemm_qkv<<<dim3(8, 32, 3), 512, 81920>>>(q, k, v, Wk, bk, Wv, bv);

    dv_kernel<<<(B_ * S_ * S_) / 256, 256>>>(pdiff);

    scores_mma<<<dim3(10, BH_), 256, 73728>>>();

    row_kernel<<<dim3(S_ / 8, BH_), 256>>>(gammas);

    pv_mma<<<dim3(4, BH_), 256, 46080>>>();

    gemm_out<<<dim3(8, 32), 512, 81920>>>(att, Wo, bo, out);
}

// round 16
// speedup vs baseline: 1.0721x; 1.0213x over previous
#include <cuda_runtime.h>
#include <cuda_bf16.h>
#include <cuda_fp16.h>
#include <math.h>
#include <stdint.h>

#define B_  8
#define S_  512
#define D_  1024
#define H_  16
#define DH_ 64
#define BH_ 128

// ---------------- scratch (device globals; no runtime allocation) ----------------
__device__ float g_sc [(size_t)BH_*S_*S_];            // fp32 scores
__device__ float g_att[(size_t)B_*S_*D_];             // attention out, concat [B,S,D]
__device__ float g_dv [(size_t)B_*S_*S_];             // exp(sigmoid(pdiff))
__device__ __nv_bfloat16 g_qhh[(size_t)BH_*S_*DH_], g_qhl[(size_t)BH_*S_*DH_];
__device__ __nv_bfloat16 g_khh[(size_t)BH_*S_*DH_], g_khl[(size_t)BH_*S_*DH_];
__device__ __half        g_vhh[(size_t)BH_*S_*DH_], g_vhl[(size_t)BH_*S_*DH_];   // fp16
__device__ __half        g_phi[(size_t)BH_*S_*S_],  g_plo[(size_t)BH_*S_*S_];    // fp16

// ======================= warp-level MMA + ldmatrix ================================
__device__ __forceinline__ void mma_bf16(float* c, uint32_t a0, uint32_t a1,
                                         uint32_t a2, uint32_t a3,
                                         uint32_t b0, uint32_t b1) {
    asm volatile(
        "mma.sync.aligned.m16n8k16.row.col.f32.bf16.bf16.f32 "
        "{%0,%1,%2,%3}, {%4,%5,%6,%7}, {%8,%9}, {%0,%1,%2,%3};"
        : "+f"(c[0]), "+f"(c[1]), "+f"(c[2]), "+f"(c[3])
        : "r"(a0), "r"(a1), "r"(a2), "r"(a3), "r"(b0), "r"(b1));
}
__device__ __forceinline__ void mma_f16(float* c, uint32_t a0, uint32_t a1,
                                        uint32_t a2, uint32_t a3,
                                        uint32_t b0, uint32_t b1) {
    asm volatile(
        "mma.sync.aligned.m16n8k16.row.col.f32.f16.f16.f32 "
        "{%0,%1,%2,%3}, {%4,%5,%6,%7}, {%8,%9}, {%0,%1,%2,%3};"
        : "+f"(c[0]), "+f"(c[1]), "+f"(c[2]), "+f"(c[3])
        : "r"(a0), "r"(a1), "r"(a2), "r"(a3), "r"(b0), "r"(b1));
}
__device__ __forceinline__ uint32_t smem_u32(const void* p) {
    uint32_t a;
    asm("{ .reg .u64 t; cvta.to.shared.u64 t, %1; cvt.u32.u64 %0, t; }" : "=r"(a) : "l"(p));
    return a;
}
__device__ __forceinline__ void ldsm_x4(uint32_t& r0, uint32_t& r1, uint32_t& r2,
                                        uint32_t& r3, uint32_t a) {
    asm volatile("ldmatrix.sync.aligned.m8n8.x4.shared.b16 {%0,%1,%2,%3}, [%4];"
                 : "=r"(r0), "=r"(r1), "=r"(r2), "=r"(r3) : "r"(a));
}
__device__ __forceinline__ void ldsm_x2(uint32_t& r0, uint32_t& r1, uint32_t a) {
    asm volatile("ldmatrix.sync.aligned.m8n8.x2.shared.b16 {%0,%1}, [%2];"
                 : "=r"(r0), "=r"(r1) : "r"(a));
}
__device__ __forceinline__ uint32_t pack_bf16(float x, float y) {
    __nv_bfloat162 t = __floats2bfloat162_rn(x, y);
    return *(uint32_t*)&t;
}
__device__ __forceinline__ uint32_t pack_f16(float x, float y) {
    __half2 t = __floats2half2_rn(x, y);
    return *(uint32_t*)&t;
}
__device__ __forceinline__ void split4(float4 v, uint32_t& h0, uint32_t& h1,
                                       uint32_t& l0, uint32_t& l1) {
    h0 = pack_bf16(v.x, v.y);
    h1 = pack_bf16(v.z, v.w);
    __nv_bfloat162 hh0 = *(__nv_bfloat162*)&h0;
    __nv_bfloat162 hh1 = *(__nv_bfloat162*)&h1;
    l0 = pack_bf16(v.x - __bfloat162float(hh0.x), v.y - __bfloat162float(hh0.y));
    l1 = pack_bf16(v.z - __bfloat162float(hh1.x), v.w - __bfloat162float(hh1.y));
}
__device__ __forceinline__ void split4h(float4 v, uint32_t& h0, uint32_t& h1,
                                        uint32_t& l0, uint32_t& l1) {
    __half2 a = __floats2half2_rn(v.x, v.y);
    __half2 b = __floats2half2_rn(v.z, v.w);
    h0 = *(uint32_t*)&a;
    h1 = *(uint32_t*)&b;
    __half2 la = __floats2half2_rn(v.x - __half2float(__low2half(a)),
                                   v.y - __half2float(__high2half(a)));
    __half2 lb = __floats2half2_rn(v.z - __half2float(__low2half(b)),
                                   v.w - __half2float(__high2half(b)));
    l0 = *(uint32_t*)&la;
    l1 = *(uint32_t*)&lb;
}

// ==================================================================================
// Double-buffered emulated-fp32 GEMM (R13 config), 512 threads, LDSM fragments.
// EMU=0: bf16 3-pass; EMU=1: fp16 2-pass.  Block 128x128, BK=32, warp grid 4x4.
// ==================================================================================
#define PADW 20
#define STG  10240

template<bool PAIR, int EMU>
__device__ __forceinline__ void gemm_body(const float* __restrict__ A,
                                          const float* __restrict__ W,
                                          const float* __restrict__ bias,
                                          float* outF, void* outHv, void* outLv,
                                          int m0, int n0, uint32_t* dsm)
{
    int tid = threadIdx.x, lane = tid & 31, wid = tid >> 5;
    int wm = wid >> 2, wn = wid & 3;
    int lq = lane >> 2, tq = lane & 3;

    uint32_t sbase = smem_u32(dsm);
    int sub     = lane >> 3;
    int arow_t  = ((sub & 1) << 3) + (lane & 7);
    int aword_t = (sub >> 1) << 2;
    int brow_t  = lane & 7;
    int bword_t = ((lane >> 3) & 1) << 2;

    float acc[2][4][4];
    #pragma unroll
    for (int mt = 0; mt < 2; mt++)
        #pragma unroll
        for (int nt = 0; nt < 4; nt++)
            #pragma unroll
            for (int e = 0; e < 4; e++) acc[mt][nt][e] = 0.f;

    int rowr[2], cqr[2], wofs[2];
    #pragma unroll
    for (int r = 0; r < 2; r++) {
        int g = tid + r * 512;
        rowr[r] = g >> 3;
        cqr[r]  = g & 7;
        wofs[r] = rowr[r] * PADW + cqr[r] * 2;
    }

    float4 va[2], vb[2];
    auto fetch = [&](int kc) {
        int k0 = kc * 32;
        #pragma unroll
        for (int r = 0; r < 2; r++) {
            va[r] = *(const float4*)(A + (size_t)(m0 + rowr[r]) * D_ + k0 + cqr[r] * 4);
            vb[r] = *(const float4*)(W + (size_t)(n0 + rowr[r]) * D_ + k0 + cqr[r] * 4);
        }
    };
    auto cvtstore = [&](uint32_t* base) {
        #pragma unroll
        for (int r = 0; r < 2; r++) {
            uint32_t h0, h1, l0, l1;
            if (EMU == 0) split4 (va[r], h0, h1, l0, l1);
            else          split4h(va[r], h0, h1, l0, l1);
            base[wofs[r]]        = h0; base[wofs[r] + 1]        = h1;
            base[2560 + wofs[r]] = l0; base[2560 + wofs[r] + 1] = l1;
            if (EMU == 0) split4 (vb[r], h0, h1, l0, l1);
            else          split4h(vb[r], h0, h1, l0, l1);
            base[5120 + wofs[r]] = h0; base[5120 + wofs[r] + 1] = h1;
            if (EMU == 0) {
                base[7680 + wofs[r]] = l0; base[7680 + wofs[r] + 1] = l1;
            }
        }
    };

    fetch(0);
    cvtstore(dsm);
    int stage = 0;

    for (int kc = 0; kc < 32; kc++) {
        __syncthreads();
        if (kc < 31) fetch(kc + 1);
        uint32_t sb = sbase + stage * (STG * 4);
        #pragma unroll
        for (int ks = 0; ks < 2; ks++) {
            uint32_t bh[4][2], bl[4][2];
            #pragma unroll
            for (int nt = 0; nt < 4; nt++) {
                uint32_t ba = sb + ((5120 + (wn * 32 + nt * 8 + brow_t) * PADW
                                     + ks * 8 + bword_t) << 2);
                ldsm_x2(bh[nt][0], bh[nt][1], ba);
                if (EMU == 0) ldsm_x2(bl[nt][0], bl[nt][1], ba + (2560 << 2));
            }
            #pragma unroll
            for (int mt = 0; mt < 2; mt++) {
                uint32_t aa = sb + (((wm * 32 + mt * 16 + arow_t) * PADW
                                     + ks * 8 + aword_t) << 2);
                uint32_t ah0, ah1, ah2, ah3, al0, al1, al2, al3;
                ldsm_x4(ah0, ah1, ah2, ah3, aa);
                ldsm_x4(al0, al1, al2, al3, aa + (2560 << 2));
                #pragma unroll
                for (int nt = 0; nt < 4; nt++) {
                    if (EMU == 0) {
                        mma_bf16(acc[mt][nt], ah0, ah1, ah2, ah3, bh[nt][0], bh[nt][1]);
                        mma_bf16(acc[mt][nt], ah0, ah1, ah2, ah3, bl[nt][0], bl[nt][1]);
                        mma_bf16(acc[mt][nt], al0, al1, al2, al3, bh[nt][0], bh[nt][1]);
                    } else {
                        mma_f16(acc[mt][nt], ah0, ah1, ah2, ah3, bh[nt][0], bh[nt][1]);
                        mma_f16(acc[mt][nt], al0, al1, al2, al3, bh[nt][0], bh[nt][1]);
                    }
                }
            }
        }
        if (kc < 31) cvtstore(dsm + (stage ^ 1) * STG);
        stage ^= 1;
    }

    #pragma unroll
    for (int mt = 0; mt < 2; mt++) {
        #pragma unroll
        for (int nt = 0; nt < 4; nt++) {
            int n = n0 + wn * 32 + nt * 8 + tq * 2;
            float b0v = __ldg(bias + n), b1v = __ldg(bias + n + 1);
            #pragma unroll
            for (int hf = 0; hf < 2; hf++) {
                int m = m0 + wm * 32 + mt * 16 + lq + hf * 8;
                float v0 = acc[mt][nt][hf * 2 + 0] + b0v;
                float v1 = acc[mt][nt][hf * 2 + 1] + b1v;
                if (PAIR) {
                    int bb = m / S_, srow = m % S_;
                    int h = n >> 6, d = n & 63;
                    size_t idx = (((size_t)bb * H_ + h) * S_ + srow) * DH_ + d;
                    if (EMU == 0) {
                        __nv_bfloat16 h0 = __float2bfloat16(v0);
                        __nv_bfloat16 h1 = __float2bfloat16(v1);
                        __nv_bfloat162 hv; hv.x = h0; hv.y = h1;
                        __nv_bfloat162 lv;
                        lv.x = __float2bfloat16(v0 - __bfloat162float(h0));
                        lv.y = __float2bfloat16(v1 - __bfloat162float(h1));
                        *(__nv_bfloat162*)((__nv_bfloat16*)outHv + idx) = hv;
                        *(__nv_bfloat162*)((__nv_bfloat16*)outLv + idx) = lv;
                    } else {
                        __half h0 = __float2half(v0);
                        __half h1 = __float2half(v1);
                        __half2 hv; hv.x = h0; hv.y = h1;
                        __half2 lv;
                        lv.x = __float2half(v0 - __half2float(h0));
                        lv.y = __float2half(v1 - __half2float(h1));
                        *(__half2*)((__half*)outHv + idx) = hv;
                        *(__half2*)((__half*)outLv + idx) = lv;
                    }
                } else {
                    *(float2*)&outF[(size_t)m * D_ + n] = make_float2(v0, v1);
                }
            }
        }
    }
}

__global__ __launch_bounds__(512, 1)
void gemm_qkv(const float* __restrict__ q, const float* __restrict__ k,
              const float* __restrict__ v, const float* __restrict__ Wk,
              const float* __restrict__ bk, const float* __restrict__ Wv,
              const float* __restrict__ bv)
{
    extern __shared__ __align__(16) uint32_t dsm[];
    int z = blockIdx.z;
    if (z == 2) {
        gemm_body<true, 1>(v, Wv, bv, nullptr, g_vhh, g_vhl,
                           blockIdx.y * 128, blockIdx.x * 128, dsm);
    } else {
        const float* A    = (z == 0) ? q : k;
        __nv_bfloat16* oh = (z == 0) ? g_qhh : g_khh;
        __nv_bfloat16* ol = (z == 0) ? g_qhl : g_khl;
        gemm_body<true, 0>(A, Wk, bk, nullptr, oh, ol,
                           blockIdx.y * 128, blockIdx.x * 128, dsm);
    }
}

__global__ __launch_bounds__(512, 1)
void gemm_out(const float* __restrict__ A, const float* __restrict__ W,
              const float* __restrict__ bias, float* __restrict__ out)
{
    extern __shared__ __align__(16) uint32_t dsm[];
    gemm_body<false, 1>(A, W, bias, out, nullptr, nullptr,
                        blockIdx.y * 128, blockIdx.x * 128, dsm);
}

// ==================================================================================
// Scores via MMA (bf16x3), grid 10 x 128. (R13, unchanged)
// ==================================================================================
#define PADS 36

__global__ __launch_bounds__(256, 1)
void scores_mma()
{
    extern __shared__ __align__(16) uint32_t sm[];
    uint32_t* sQh = sm;
    uint32_t* sQl = sm + 4608;
    uint32_t* sKh = sm + 9216;
    uint32_t* sKl = sm + 13824;

    int z = blockIdx.y;
    int t = blockIdx.x;
    int mi = (t < 1) ? 0 : (t < 3) ? 1 : (t < 6) ? 2 : 3;
    int ni = t - mi * (mi + 1) / 2;
    int m0 = mi * 128, n0 = ni * 128;

    int tid = threadIdx.x, lane = tid & 31, wid = tid >> 5;
    int wm = wid >> 2, wn = wid & 3, lq = lane >> 2, tq = lane & 3;

    uint32_t sbase = smem_u32(sm);
    int sub     = lane >> 3;
    int arow_t  = ((sub & 1) << 3) + (lane & 7);
    int aword_t = (sub >> 1) << 2;
    int brow_t  = lane & 7;
    int bword_t = ((lane >> 3) & 1) << 2;

    const uint32_t* qh = (const uint32_t*)(g_qhh + (size_t)z * S_ * DH_);
    const uint32_t* ql = (const uint32_t*)(g_qhl + (size_t)z * S_ * DH_);
    const uint32_t* kh = (const uint32_t*)(g_khh + (size_t)z * S_ * DH_);
    const uint32_t* kl = (const uint32_t*)(g_khl + (size_t)z * S_ * DH_);

    {
        int row = tid >> 1, hf = tid & 1;
        int gq = (m0 + row) * 32 + hf * 16;
        int gk = (n0 + row) * 32 + hf * 16;
        int so = row * PADS + hf * 16;
        #pragma unroll
        for (int qd = 0; qd < 4; qd++) {
            *(uint4*)(sQh + so + qd * 4) = *(const uint4*)(qh + gq + qd * 4);
            *(uint4*)(sQl + so + qd * 4) = *(const uint4*)(ql + gq + qd * 4);
            *(uint4*)(sKh + so + qd * 4) = *(const uint4*)(kh + gk + qd * 4);
            *(uint4*)(sKl + so + qd * 4) = *(const uint4*)(kl + gk + qd * 4);
        }
    }
    __syncthreads();

    float acc[4][4][4];
    #pragma unroll
    for (int mt = 0; mt < 4; mt++)
        #pragma unroll
        for (int nt = 0; nt < 4; nt++)
            #pragma unroll
            for (int e = 0; e < 4; e++) acc[mt][nt][e] = 0.f;

    #pragma unroll
    for (int ks = 0; ks < 4; ks++) {
        uint32_t bh[4][2], bl[4][2];
        #pragma unroll
        for (int nt = 0; nt < 4; nt++) {
            uint32_t ba = sbase + ((9216 + (wn * 32 + nt * 8 + brow_t) * PADS
                                    + ks * 8 + bword_t) << 2);
            ldsm_x2(bh[nt][0], bh[nt][1], ba);
            ldsm_x2(bl[nt][0], bl[nt][1], ba + (4608 << 2));
        }
        #pragma unroll
        for (int mt = 0; mt < 4; mt++) {
            uint32_t aa = sbase + (((wm * 64 + mt * 16 + arow_t) * PADS
                                    + ks * 8 + aword_t) << 2);
            uint32_t ah0, ah1, ah2, ah3, al0, al1, al2, al3;
            ldsm_x4(ah0, ah1, ah2, ah3, aa);
            ldsm_x4(al0, al1, al2, al3, aa + (4608 << 2));
            #pragma unroll
            for (int nt = 0; nt < 4; nt++) {
                mma_bf16(acc[mt][nt], ah0, ah1, ah2, ah3, bh[nt][0], bh[nt][1]);
                mma_bf16(acc[mt][nt], ah0, ah1, ah2, ah3, bl[nt][0], bl[nt][1]);
                mma_bf16(acc[mt][nt], al0, al1, al2, al3, bh[nt][0], bh[nt][1]);
            }
        }
    }

    float* C = g_sc + (size_t)z * S_ * S_;
    #pragma unroll
    for (int mt = 0; mt < 4; mt++) {
        #pragma unroll
        for (int nt = 0; nt < 4; nt++) {
            int j = n0 + wn * 32 + nt * 8 + tq * 2;
            #pragma unroll
            for (int hf = 0; hf < 2; hf++) {
                int i = m0 + wm * 64 + mt * 16 + lq + hf * 8;
                *(float2*)&C[(size_t)i * S_ + j] =
                    make_float2(acc[mt][nt][hf * 2] * 0.125f,
                                acc[mt][nt][hf * 2 + 1] * 0.125f);
            }
        }
    }
}

// ==================================================================================
// dv precompute
// ==================================================================================
__global__ __launch_bounds__(256)
void dv_kernel(const float* __restrict__ pdiff)
{
    size_t idx = (size_t)blockIdx.x * 256 + threadIdx.x;
    float x = pdiff[idx];
    float sig = 1.f / (1.f + __expf(-x));
    g_dv[idx] = __expf(sig);
}

// ==================================================================================
// Row kernel (R13, unchanged): vectorized, fp16 hi/lo P output.
// ==================================================================================
__global__ __launch_bounds__(256)
void row_kernel(const float* __restrict__ gammas)
{
    int warp = threadIdx.x >> 5, lane = threadIdx.x & 31;
    int i = blockIdx.x * 8 + warp;
    int z = blockIdx.y;
    int b = z >> 4, h = z & 15;

    const float* row   = g_sc + ((size_t)z * S_ + i) * S_;
    const float* dvrow = g_dv + ((size_t)b * S_ + i) * S_;

    int nc4 = (i >> 7) + 1;
    float4 scv[4], s2v[4];

    #pragma unroll
    for (int c = 0; c < 4; c++)
        if (c < nc4) scv[c] = *(const float4*)(row + c * 128 + lane * 4);

    float run = 0.f;
    #pragma unroll
    for (int c = 0; c < 4; c++) {
        if (c < nc4) {
            int j0 = c * 128 + lane * 4;
            float p0 = (j0 + 0 <= i) ? __expf(scv[c].x) : 0.f;
            float p1 = (j0 + 1 <= i) ? __expf(scv[c].y) : 0.f;
            float p2 = (j0 + 2 <= i) ? __expf(scv[c].z) : 0.f;
            float p3 = (j0 + 3 <= i) ? __expf(scv[c].w) : 0.f;
            float q1 = p0 + p1;
            float q2 = q1 + p2;
            float q3 = q2 + p3;
            float s = q3;
            #pragma unroll
            for (int d = 1; d < 32; d <<= 1) {
                float tt = __shfl_up_sync(0xFFFFFFFFu, s, d);
                if (lane >= d) s += tt;
            }
            float excl = run + (s - q3);
            s2v[c].x = excl + p0;
            s2v[c].y = excl + q1;
            s2v[c].z = excl + q2;
            s2v[c].w = excl + q3;
            run += __shfl_sync(0xFFFFFFFFu, s, 31);
        }
    }
    float tot  = run;
    float rtot = 1.f / fmaxf(tot, 1e-30f);

    float g = gammas[h];
    float gamma = -log1pf(__expf(g));

    float4 dvv[4];
    #pragma unroll
    for (int c = 0; c < 4; c++)
        if (c < nc4) dvv[c] = *(const float4*)(dvrow + c * 128 + lane * 4);

    float sum2 = 0.f;
    #pragma unroll
    for (int c = 0; c < 4; c++) {
        if (c < nc4) {
            int j0 = c * 128 + lane * 4;
            float e[4];
            float sc[4] = {scv[c].x, scv[c].y, scv[c].z, scv[c].w};
            float cu[4] = {s2v[c].x, s2v[c].y, s2v[c].z, s2v[c].w};
            float dv[4] = {dvv[c].x, dvv[c].y, dvv[c].z, dvv[c].w};
            #pragma unroll
            for (int e4 = 0; e4 < 4; e4++) {
                int j = j0 + e4;
                float rem  = fmaxf(tot - cu[e4], 0.f) * rtot;
                float pos  = (float)(i - j);
                float dist = sqrtf(fmaxf(rem * pos, 0.f));
                float eff  = fmaxf(__expf(dist * gamma * dv[e4]), 1e-5f);
                float s2 = sc[e4] * eff;
                e[e4] = (j <= i) ? __expf(s2) : 0.f;
                sum2 += e[e4];
            }
            s2v[c] = make_float4(e[0], e[1], e[2], e[3]);
        }
    }
    #pragma unroll
    for (int o = 16; o > 0; o >>= 1) sum2 += __shfl_xor_sync(0xFFFFFFFFu, sum2, o);

    float rs = (i == 0) ? 0.f : 1.f / sum2;

    __half* ph = g_phi + ((size_t)z * S_ + i) * S_;
    __half* pl = g_plo + ((size_t)z * S_ + i) * S_;
    #pragma unroll
    for (int c = 0; c < 4; c++) {
        if (c < nc4) {
            int j0 = c * 128 + lane * 4;
            float p0 = s2v[c].x * rs, p1 = s2v[c].y * rs;
            float p2 = s2v[c].z * rs, p3 = s2v[c].w * rs;
            uint32_t h01 = pack_f16(p0, p1), h23 = pack_f16(p2, p3);
            __half2 hh01 = *(__half2*)&h01;
            __half2 hh23 = *(__half2*)&h23;
            uint32_t l01 = pack_f16(p0 - __half2float(hh01.x),
                                    p1 - __half2float(hh01.y));
            uint32_t l23 = pack_f16(p2 - __half2float(hh23.x),
                                    p3 - __half2float(hh23.y));
            *(uint2*)(ph + j0) = make_uint2(h01, h23);
            *(uint2*)(pl + j0) = make_uint2(l01, l23);
        }
    }
}

// ==================================================================================
// PV via MMA, fp16 2-pass (R13 staging), OCCUPANCY 2. 128(M) x 64(N).
// ==================================================================================
__global__ __launch_bounds__(256, 2)
void pv_mma()
{
    extern __shared__ __align__(16) uint32_t sm[];
    uint32_t* sPh = sm;
    uint32_t* sPl = sm + 4608;
    uint32_t* sVh = sm + 9216;
    __half* sVh16 = (__half*)sVh;

    int z  = blockIdx.y;
    int b  = z >> 4, h = z & 15;
    int m0 = (3 - (int)blockIdx.x) * 128;

    int tid = threadIdx.x, lane = tid & 31, wid = tid >> 5;
    int wm = wid >> 2, wn = wid & 3, lq = lane >> 2, tq = lane & 3;

    const uint32_t* pwh = (const uint32_t*)(g_phi + (size_t)z * S_ * S_);
    const uint32_t* pwl = (const uint32_t*)(g_plo + (size_t)z * S_ * S_);
    const uint32_t* vwh = (const uint32_t*)(g_vhh + (size_t)z * S_ * DH_);

    float acc[4][2][4];
    #pragma unroll
    for (int mt = 0; mt < 4; mt++)
        #pragma unroll
        for (int nt = 0; nt < 2; nt++)
            #pragma unroll
            for (int e = 0; e < 4; e++) acc[mt][nt][e] = 0.f;

    int nchunks = m0 / 64 + 2;

    for (int c = 0; c < nchunks; c++) {
        int k0 = c * 64;
        {
            int row = tid >> 1, hf = tid & 1;
            int gofs = (m0 + row) * 256 + k0 / 2 + hf * 16;
            int so = row * PADS + hf * 16;
            #pragma unroll
            for (int qd = 0; qd < 4; qd++) {
                *(uint4*)(sPh + so + qd * 4) = *(const uint4*)(pwh + gofs + qd * 4);
                *(uint4*)(sPl + so + qd * 4) = *(const uint4*)(pwl + gofs + qd * 4);
            }
        }
        {
            int r  = tid >> 2;
            int w0 = (tid & 3) * 8;
            #pragma unroll
            for (int qd = 0; qd < 2; qd++) {
                uint4 vv = *(const uint4*)(vwh + (k0 + r) * 32 + w0 + qd * 4);
                uint32_t wv[4] = {vv.x, vv.y, vv.z, vv.w};
                #pragma unroll
                for (int q2 = 0; q2 < 4; q2++) {
                    int d0 = (w0 + qd * 4 + q2) * 2;
                    __half2 pr = *(__half2*)&wv[q2];
                    sVh16[d0 * 72 + r]       = pr.x;
                    sVh16[(d0 + 1) * 72 + r] = pr.y;
                }
            }
        }
        __syncthreads();

        #pragma unroll
        for (int ks = 0; ks < 4; ks++) {
            int kofs = ks * 8 + tq;
            uint32_t bh[2][2];
            #pragma unroll
            for (int nt = 0; nt < 2; nt++) {
                int bi = (wn * 16 + nt * 8 + lq) * PADS + kofs;
                bh[nt][0] = sVh[bi]; bh[nt][1] = sVh[bi + 4];
            }
            #pragma unroll
            for (int mt = 0; mt < 4; mt++) {
                int ai = (wm * 64 + mt * 16 + lq) * PADS + kofs;
                uint32_t ah0 = sPh[ai],     ah1 = sPh[ai + 8 * PADS];
                uint32_t ah2 = sPh[ai + 4], ah3 = sPh[ai + 8 * PADS + 4];
                uint32_t al0 = sPl[ai],     al1 = sPl[ai + 8 * PADS];
                uint32_t al2 = sPl[ai + 4], al3 = sPl[ai + 8 * PADS + 4];
                #pragma unroll
                for (int nt = 0; nt < 2; nt++) {
                    mma_f16(acc[mt][nt], ah0, ah1, ah2, ah3, bh[nt][0], bh[nt][1]);
                    mma_f16(acc[mt][nt], al0, al1, al2, al3, bh[nt][0], bh[nt][1]);
                }
            }
        }
        __syncthreads();
    }

    #pragma unroll
    for (int mt = 0; mt < 4; mt++) {
        #pragma unroll
        for (int nt = 0; nt < 2; nt++) {
            int d = wn * 16 + nt * 8 + tq * 2;
            #pragma unroll
            for (int hf = 0; hf < 2; hf++) {
                int i = m0 + wm * 64 + mt * 16 + lq + hf * 8;
                *(float2*)&g_att[((size_t)b * S_ + i) * D_ + h * DH_ + d] =
                    make_float2(acc[mt][nt][hf * 2], acc[mt][nt][hf * 2 + 1]);
            }
        }
    }
}

// ==================================================================================
extern "C" void kernel_launch(void* const* d_in, const int* in_sizes, int n_in,
                              void* d_out, int out_size)
{
    const float* q      = (const float*)d_in[0];
    const float* k      = (const float*)d_in[1];
    const float* v      = (const float*)d_in[2];
    const float* pdiff  = (const float*)d_in[3];
    const float* Wk     = (const float*)d_in[4];
    const float* bk     = (const float*)d_in[5];
    const float* Wv     = (const float*)d_in[6];
    const float* bv     = (const float*)d_in[7];
    const float* Wo     = (const float*)d_in[8];
    const float* bo     = (const float*)d_in[9];
    const float* gammas = (const float*)d_in[10];
    float* out = (float*)d_out;

    float* att;
    cudaGetSymbolAddress((void**)&att, g_att);

    cudaFuncSetAttribute(gemm_qkv,   cudaFuncAttributeMaxDynamicSharedMemorySize, 81920);
    cudaFuncSetAttribute(gemm_out,   cudaFuncAttributeMaxDynamicSharedMemorySize, 81920);
    cudaFuncSetAttribute(scores_mma, cudaFuncAttributeMaxDynamicSharedMemorySize, 73728);
    cudaFuncSetAttribute(pv_mma,     cudaFuncAttributeMaxDynamicSharedMemorySize, 46080);

    gemm_qkv<<<dim3(8, 32, 3), 512, 81920>>>(q, k, v, Wk, bk, Wv, bv);

    dv_kernel<<<(B_ * S_ * S_) / 256, 256>>>(pdiff);

    scores_mma<<<dim3(10, BH_), 256, 73728>>>();

    row_kernel<<<dim3(S_ / 8, BH_), 256>>>(gammas);

    pv_mma<<<dim3(4, BH_), 256, 46080>>>();

    gemm_out<<<dim3(8, 32), 512, 81920>>>(att, Wo, bo, out);
}

// round 17
// speedup vs baseline: 1.0916x; 1.0181x over previous
#include <cuda_runtime.h>
#include <cuda_bf16.h>
#include <cuda_fp16.h>
#include <math.h>
#include <stdint.h>

#define B_  8
#define S_  512
#define D_  1024
#define H_  16
#define DH_ 64
#define BH_ 128

// ---------------- scratch (device globals; no runtime allocation) ----------------
__device__ float g_sc [(size_t)BH_*S_*S_];            // fp32 scores
__device__ float g_att[(size_t)B_*S_*D_];             // attention out, concat [B,S,D]
__device__ float g_dv [(size_t)B_*S_*S_];             // exp(sigmoid(pdiff))
__device__ __nv_bfloat16 g_qhh[(size_t)BH_*S_*DH_], g_qhl[(size_t)BH_*S_*DH_];
__device__ __nv_bfloat16 g_khh[(size_t)BH_*S_*DH_], g_khl[(size_t)BH_*S_*DH_];
__device__ __half        g_vhh[(size_t)BH_*S_*DH_], g_vhl[(size_t)BH_*S_*DH_];   // fp16
__device__ __half        g_phi[(size_t)BH_*S_*S_],  g_plo[(size_t)BH_*S_*S_];    // fp16

// ======================= warp-level MMA + ldmatrix ================================
__device__ __forceinline__ void mma_bf16(float* c, uint32_t a0, uint32_t a1,
                                         uint32_t a2, uint32_t a3,
                                         uint32_t b0, uint32_t b1) {
    asm volatile(
        "mma.sync.aligned.m16n8k16.row.col.f32.bf16.bf16.f32 "
        "{%0,%1,%2,%3}, {%4,%5,%6,%7}, {%8,%9}, {%0,%1,%2,%3};"
        : "+f"(c[0]), "+f"(c[1]), "+f"(c[2]), "+f"(c[3])
        : "r"(a0), "r"(a1), "r"(a2), "r"(a3), "r"(b0), "r"(b1));
}
__device__ __forceinline__ void mma_f16(float* c, uint32_t a0, uint32_t a1,
                                        uint32_t a2, uint32_t a3,
                                        uint32_t b0, uint32_t b1) {
    asm volatile(
        "mma.sync.aligned.m16n8k16.row.col.f32.f16.f16.f32 "
        "{%0,%1,%2,%3}, {%4,%5,%6,%7}, {%8,%9}, {%0,%1,%2,%3};"
        : "+f"(c[0]), "+f"(c[1]), "+f"(c[2]), "+f"(c[3])
        : "r"(a0), "r"(a1), "r"(a2), "r"(a3), "r"(b0), "r"(b1));
}
__device__ __forceinline__ uint32_t smem_u32(const void* p) {
    uint32_t a;
    asm("{ .reg .u64 t; cvta.to.shared.u64 t, %1; cvt.u32.u64 %0, t; }" : "=r"(a) : "l"(p));
    return a;
}
__device__ __forceinline__ void ldsm_x4(uint32_t& r0, uint32_t& r1, uint32_t& r2,
                                        uint32_t& r3, uint32_t a) {
    asm volatile("ldmatrix.sync.aligned.m8n8.x4.shared.b16 {%0,%1,%2,%3}, [%4];"
                 : "=r"(r0), "=r"(r1), "=r"(r2), "=r"(r3) : "r"(a));
}
__device__ __forceinline__ void ldsm_x2(uint32_t& r0, uint32_t& r1, uint32_t a) {
    asm volatile("ldmatrix.sync.aligned.m8n8.x2.shared.b16 {%0,%1}, [%2];"
                 : "=r"(r0), "=r"(r1) : "r"(a));
}
__device__ __forceinline__ uint32_t pack_bf16(float x, float y) {
    __nv_bfloat162 t = __floats2bfloat162_rn(x, y);
    return *(uint32_t*)&t;
}
__device__ __forceinline__ uint32_t pack_f16(float x, float y) {
    __half2 t = __floats2half2_rn(x, y);
    return *(uint32_t*)&t;
}
__device__ __forceinline__ void split4(float4 v, uint32_t& h0, uint32_t& h1,
                                       uint32_t& l0, uint32_t& l1) {
    h0 = pack_bf16(v.x, v.y);
    h1 = pack_bf16(v.z, v.w);
    __nv_bfloat162 hh0 = *(__nv_bfloat162*)&h0;
    __nv_bfloat162 hh1 = *(__nv_bfloat162*)&h1;
    l0 = pack_bf16(v.x - __bfloat162float(hh0.x), v.y - __bfloat162float(hh0.y));
    l1 = pack_bf16(v.z - __bfloat162float(hh1.x), v.w - __bfloat162float(hh1.y));
}
__device__ __forceinline__ void split4h(float4 v, uint32_t& h0, uint32_t& h1,
                                        uint32_t& l0, uint32_t& l1) {
    __half2 a = __floats2half2_rn(v.x, v.y);
    __half2 b = __floats2half2_rn(v.z, v.w);
    h0 = *(uint32_t*)&a;
    h1 = *(uint32_t*)&b;
    __half2 la = __floats2half2_rn(v.x - __half2float(__low2half(a)),
                                   v.y - __half2float(__high2half(a)));
    __half2 lb = __floats2half2_rn(v.z - __half2float(__low2half(b)),
                                   v.w - __half2float(__high2half(b)));
    l0 = *(uint32_t*)&la;
    l1 = *(uint32_t*)&lb;
}

// ==================================================================================
// Double-buffered emulated-fp32 GEMM, 512 threads, LDSM fragments.
// EMU=0: bf16 3-pass; EMU=1: fp16 2-pass.  Block 128x128, BK=32, warp grid 4x4.
// ==================================================================================
#define PADW 20
#define STG  10240

template<bool PAIR, int EMU>
__device__ __forceinline__ void gemm_body(const float* __restrict__ A,
                                          const float* __restrict__ W,
                                          const float* __restrict__ bias,
                                          float* outF, void* outHv, void* outLv,
                                          int m0, int n0, uint32_t* dsm)
{
    int tid = threadIdx.x, lane = tid & 31, wid = tid >> 5;
    int wm = wid >> 2, wn = wid & 3;
    int lq = lane >> 2, tq = lane & 3;

    uint32_t sbase = smem_u32(dsm);
    int sub     = lane >> 3;
    int arow_t  = ((sub & 1) << 3) + (lane & 7);
    int aword_t = (sub >> 1) << 2;
    int brow_t  = lane & 7;
    int bword_t = ((lane >> 3) & 1) << 2;

    float acc[2][4][4];
    #pragma unroll
    for (int mt = 0; mt < 2; mt++)
        #pragma unroll
        for (int nt = 0; nt < 4; nt++)
            #pragma unroll
            for (int e = 0; e < 4; e++) acc[mt][nt][e] = 0.f;

    int rowr[2], cqr[2], wofs[2];
    #pragma unroll
    for (int r = 0; r < 2; r++) {
        int g = tid + r * 512;
        rowr[r] = g >> 3;
        cqr[r]  = g & 7;
        wofs[r] = rowr[r] * PADW + cqr[r] * 2;
    }

    float4 va[2], vb[2];
    auto fetch = [&](int kc) {
        int k0 = kc * 32;
        #pragma unroll
        for (int r = 0; r < 2; r++) {
            va[r] = *(const float4*)(A + (size_t)(m0 + rowr[r]) * D_ + k0 + cqr[r] * 4);
            vb[r] = *(const float4*)(W + (size_t)(n0 + rowr[r]) * D_ + k0 + cqr[r] * 4);
        }
    };
    auto cvtstore = [&](uint32_t* base) {
        #pragma unroll
        for (int r = 0; r < 2; r++) {
            uint32_t h0, h1, l0, l1;
            if (EMU == 0) split4 (va[r], h0, h1, l0, l1);
            else          split4h(va[r], h0, h1, l0, l1);
            base[wofs[r]]        = h0; base[wofs[r] + 1]        = h1;
            base[2560 + wofs[r]] = l0; base[2560 + wofs[r] + 1] = l1;
            if (EMU == 0) split4 (vb[r], h0, h1, l0, l1);
            else          split4h(vb[r], h0, h1, l0, l1);
            base[5120 + wofs[r]] = h0; base[5120 + wofs[r] + 1] = h1;
            if (EMU == 0) {
                base[7680 + wofs[r]] = l0; base[7680 + wofs[r] + 1] = l1;
            }
        }
    };

    fetch(0);
    cvtstore(dsm);
    int stage = 0;

    for (int kc = 0; kc < 32; kc++) {
        __syncthreads();
        if (kc < 31) fetch(kc + 1);
        uint32_t sb = sbase + stage * (STG * 4);
        #pragma unroll
        for (int ks = 0; ks < 2; ks++) {
            uint32_t bh[4][2], bl[4][2];
            #pragma unroll
            for (int nt = 0; nt < 4; nt++) {
                uint32_t ba = sb + ((5120 + (wn * 32 + nt * 8 + brow_t) * PADW
                                     + ks * 8 + bword_t) << 2);
                ldsm_x2(bh[nt][0], bh[nt][1], ba);
                if (EMU == 0) ldsm_x2(bl[nt][0], bl[nt][1], ba + (2560 << 2));
            }
            #pragma unroll
            for (int mt = 0; mt < 2; mt++) {
                uint32_t aa = sb + (((wm * 32 + mt * 16 + arow_t) * PADW
                                     + ks * 8 + aword_t) << 2);
                uint32_t ah0, ah1, ah2, ah3, al0, al1, al2, al3;
                ldsm_x4(ah0, ah1, ah2, ah3, aa);
                ldsm_x4(al0, al1, al2, al3, aa + (2560 << 2));
                #pragma unroll
                for (int nt = 0; nt < 4; nt++) {
                    if (EMU == 0) {
                        mma_bf16(acc[mt][nt], ah0, ah1, ah2, ah3, bh[nt][0], bh[nt][1]);
                        mma_bf16(acc[mt][nt], ah0, ah1, ah2, ah3, bl[nt][0], bl[nt][1]);
                        mma_bf16(acc[mt][nt], al0, al1, al2, al3, bh[nt][0], bh[nt][1]);
                    } else {
                        mma_f16(acc[mt][nt], ah0, ah1, ah2, ah3, bh[nt][0], bh[nt][1]);
                        mma_f16(acc[mt][nt], al0, al1, al2, al3, bh[nt][0], bh[nt][1]);
                    }
                }
            }
        }
        if (kc < 31) cvtstore(dsm + (stage ^ 1) * STG);
        stage ^= 1;
    }

    #pragma unroll
    for (int mt = 0; mt < 2; mt++) {
        #pragma unroll
        for (int nt = 0; nt < 4; nt++) {
            int n = n0 + wn * 32 + nt * 8 + tq * 2;
            float b0v = __ldg(bias + n), b1v = __ldg(bias + n + 1);
            #pragma unroll
            for (int hf = 0; hf < 2; hf++) {
                int m = m0 + wm * 32 + mt * 16 + lq + hf * 8;
                float v0 = acc[mt][nt][hf * 2 + 0] + b0v;
                float v1 = acc[mt][nt][hf * 2 + 1] + b1v;
                if (PAIR) {
                    int bb = m / S_, srow = m % S_;
                    int h = n >> 6, d = n & 63;
                    size_t idx = (((size_t)bb * H_ + h) * S_ + srow) * DH_ + d;
                    if (EMU == 0) {
                        __nv_bfloat16 h0 = __float2bfloat16(v0);
                        __nv_bfloat16 h1 = __float2bfloat16(v1);
                        __nv_bfloat162 hv; hv.x = h0; hv.y = h1;
                        __nv_bfloat162 lv;
                        lv.x = __float2bfloat16(v0 - __bfloat162float(h0));
                        lv.y = __float2bfloat16(v1 - __bfloat162float(h1));
                        *(__nv_bfloat162*)((__nv_bfloat16*)outHv + idx) = hv;
                        *(__nv_bfloat162*)((__nv_bfloat16*)outLv + idx) = lv;
                    } else {
                        __half h0 = __float2half(v0);
                        __half h1 = __float2half(v1);
                        __half2 hv; hv.x = h0; hv.y = h1;
                        __half2 lv;
                        lv.x = __float2half(v0 - __half2float(h0));
                        lv.y = __float2half(v1 - __half2float(h1));
                        *(__half2*)((__half*)outHv + idx) = hv;
                        *(__half2*)((__half*)outLv + idx) = lv;
                    }
                } else {
                    *(float2*)&outF[(size_t)m * D_ + n] = make_float2(v0, v1);
                }
            }
        }
    }
}

// z=0: q proj (bf16x3), z=1: k proj (bf16x3), z=2: v proj (fp16x2),
// z=3: dv elementwise (folded; overlaps with GEMM waves)
__global__ __launch_bounds__(512, 1)
void gemm_qkv(const float* __restrict__ q, const float* __restrict__ k,
              const float* __restrict__ v, const float* __restrict__ Wk,
              const float* __restrict__ bk, const float* __restrict__ Wv,
              const float* __restrict__ bv, const float* __restrict__ pdiff)
{
    extern __shared__ __align__(16) uint32_t dsm[];
    int z = blockIdx.z;
    if (z == 3) {
        const int TOT = B_ * S_ * S_ / 4;                 // float4 count
        int nb   = gridDim.x * gridDim.y;                 // 256 blocks
        int bidx = blockIdx.y * gridDim.x + blockIdx.x;
        for (int i4 = bidx * 512 + threadIdx.x; i4 < TOT; i4 += nb * 512) {
            float4 x = ((const float4*)pdiff)[i4];
            float4 r;
            r.x = __expf(1.f / (1.f + __expf(-x.x)));
            r.y = __expf(1.f / (1.f + __expf(-x.y)));
            r.z = __expf(1.f / (1.f + __expf(-x.z)));
            r.w = __expf(1.f / (1.f + __expf(-x.w)));
            ((float4*)g_dv)[i4] = r;
        }
        return;
    }
    if (z == 2) {
        gemm_body<true, 1>(v, Wv, bv, nullptr, g_vhh, g_vhl,
                           blockIdx.y * 128, blockIdx.x * 128, dsm);
    } else {
        const float* A    = (z == 0) ? q : k;
        __nv_bfloat16* oh = (z == 0) ? g_qhh : g_khh;
        __nv_bfloat16* ol = (z == 0) ? g_qhl : g_khl;
        gemm_body<true, 0>(A, Wk, bk, nullptr, oh, ol,
                           blockIdx.y * 128, blockIdx.x * 128, dsm);
    }
}

__global__ __launch_bounds__(512, 1)
void gemm_out(const float* __restrict__ A, const float* __restrict__ W,
              const float* __restrict__ bias, float* __restrict__ out)
{
    extern __shared__ __align__(16) uint32_t dsm[];
    gemm_body<false, 1>(A, W, bias, out, nullptr, nullptr,
                        blockIdx.y * 128, blockIdx.x * 128, dsm);
}

// ==================================================================================
// Scores via MMA (bf16x3), grid 10 x 128. (unchanged)
// ==================================================================================
#define PADS 36

__global__ __launch_bounds__(256, 1)
void scores_mma()
{
    extern __shared__ __align__(16) uint32_t sm[];
    uint32_t* sQh = sm;
    uint32_t* sQl = sm + 4608;
    uint32_t* sKh = sm + 9216;
    uint32_t* sKl = sm + 13824;

    int z = blockIdx.y;
    int t = blockIdx.x;
    int mi = (t < 1) ? 0 : (t < 3) ? 1 : (t < 6) ? 2 : 3;
    int ni = t - mi * (mi + 1) / 2;
    int m0 = mi * 128, n0 = ni * 128;

    int tid = threadIdx.x, lane = tid & 31, wid = tid >> 5;
    int wm = wid >> 2, wn = wid & 3, lq = lane >> 2, tq = lane & 3;

    uint32_t sbase = smem_u32(sm);
    int sub     = lane >> 3;
    int arow_t  = ((sub & 1) << 3) + (lane & 7);
    int aword_t = (sub >> 1) << 2;
    int brow_t  = lane & 7;
    int bword_t = ((lane >> 3) & 1) << 2;

    const uint32_t* qh = (const uint32_t*)(g_qhh + (size_t)z * S_ * DH_);
    const uint32_t* ql = (const uint32_t*)(g_qhl + (size_t)z * S_ * DH_);
    const uint32_t* kh = (const uint32_t*)(g_khh + (size_t)z * S_ * DH_);
    const uint32_t* kl = (const uint32_t*)(g_khl + (size_t)z * S_ * DH_);

    {
        int row = tid >> 1, hf = tid & 1;
        int gq = (m0 + row) * 32 + hf * 16;
        int gk = (n0 + row) * 32 + hf * 16;
        int so = row * PADS + hf * 16;
        #pragma unroll
        for (int qd = 0; qd < 4; qd++) {
            *(uint4*)(sQh + so + qd * 4) = *(const uint4*)(qh + gq + qd * 4);
            *(uint4*)(sQl + so + qd * 4) = *(const uint4*)(ql + gq + qd * 4);
            *(uint4*)(sKh + so + qd * 4) = *(const uint4*)(kh + gk + qd * 4);
            *(uint4*)(sKl + so + qd * 4) = *(const uint4*)(kl + gk + qd * 4);
        }
    }
    __syncthreads();

    float acc[4][4][4];
    #pragma unroll
    for (int mt = 0; mt < 4; mt++)
        #pragma unroll
        for (int nt = 0; nt < 4; nt++)
            #pragma unroll
            for (int e = 0; e < 4; e++) acc[mt][nt][e] = 0.f;

    #pragma unroll
    for (int ks = 0; ks < 4; ks++) {
        uint32_t bh[4][2], bl[4][2];
        #pragma unroll
        for (int nt = 0; nt < 4; nt++) {
            uint32_t ba = sbase + ((9216 + (wn * 32 + nt * 8 + brow_t) * PADS
                                    + ks * 8 + bword_t) << 2);
            ldsm_x2(bh[nt][0], bh[nt][1], ba);
            ldsm_x2(bl[nt][0], bl[nt][1], ba + (4608 << 2));
        }
        #pragma unroll
        for (int mt = 0; mt < 4; mt++) {
            uint32_t aa = sbase + (((wm * 64 + mt * 16 + arow_t) * PADS
                                    + ks * 8 + aword_t) << 2);
            uint32_t ah0, ah1, ah2, ah3, al0, al1, al2, al3;
            ldsm_x4(ah0, ah1, ah2, ah3, aa);
            ldsm_x4(al0, al1, al2, al3, aa + (4608 << 2));
            #pragma unroll
            for (int nt = 0; nt < 4; nt++) {
                mma_bf16(acc[mt][nt], ah0, ah1, ah2, ah3, bh[nt][0], bh[nt][1]);
                mma_bf16(acc[mt][nt], ah0, ah1, ah2, ah3, bl[nt][0], bl[nt][1]);
                mma_bf16(acc[mt][nt], al0, al1, al2, al3, bh[nt][0], bh[nt][1]);
            }
        }
    }

    float* C = g_sc + (size_t)z * S_ * S_;
    #pragma unroll
    for (int mt = 0; mt < 4; mt++) {
        #pragma unroll
        for (int nt = 0; nt < 4; nt++) {
            int j = n0 + wn * 32 + nt * 8 + tq * 2;
            #pragma unroll
            for (int hf = 0; hf < 2; hf++) {
                int i = m0 + wm * 64 + mt * 16 + lq + hf * 8;
                *(float2*)&C[(size_t)i * S_ + j] =
                    make_float2(acc[mt][nt][hf * 2] * 0.125f,
                                acc[mt][nt][hf * 2 + 1] * 0.125f);
            }
        }
    }
}

// ==================================================================================
// Row kernel: vectorized, fp16 hi/lo P output; full/partial chunk split
// (interior chunks skip causal predicates entirely).
// ==================================================================================
__global__ __launch_bounds__(256)
void row_kernel(const float* __restrict__ gammas)
{
    int warp = threadIdx.x >> 5, lane = threadIdx.x & 31;
    int i = blockIdx.x * 8 + warp;
    int z = blockIdx.y;
    int b = z >> 4, h = z & 15;

    const float* row   = g_sc + ((size_t)z * S_ + i) * S_;
    const float* dvrow = g_dv + ((size_t)b * S_ + i) * S_;

    int nc4   = (i >> 7) + 1;      // chunks touched
    int nfull = (i + 1) >> 7;      // chunks fully causal-valid

    float4 scv[4], s2v[4];

    #pragma unroll
    for (int c = 0; c < 4; c++)
        if (c < nc4) scv[c] = *(const float4*)(row + c * 128 + lane * 4);

    float run = 0.f;
    #pragma unroll
    for (int c = 0; c < 4; c++) {
        if (c < nc4) {
            float p0, p1, p2, p3;
            if (c < nfull) {
                p0 = __expf(scv[c].x);
                p1 = __expf(scv[c].y);
                p2 = __expf(scv[c].z);
                p3 = __expf(scv[c].w);
            } else {
                int j0 = c * 128 + lane * 4;
                p0 = (j0 + 0 <= i) ? __expf(scv[c].x) : 0.f;
                p1 = (j0 + 1 <= i) ? __expf(scv[c].y) : 0.f;
                p2 = (j0 + 2 <= i) ? __expf(scv[c].z) : 0.f;
                p3 = (j0 + 3 <= i) ? __expf(scv[c].w) : 0.f;
            }
            float q1 = p0 + p1;
            float q2 = q1 + p2;
            float q3 = q2 + p3;
            float s = q3;
            #pragma unroll
            for (int d = 1; d < 32; d <<= 1) {
                float tt = __shfl_up_sync(0xFFFFFFFFu, s, d);
                if (lane >= d) s += tt;
            }
            float excl = run + (s - q3);
            s2v[c].x = excl + p0;
            s2v[c].y = excl + q1;
            s2v[c].z = excl + q2;
            s2v[c].w = excl + q3;
            run += __shfl_sync(0xFFFFFFFFu, s, 31);
        }
    }
    float tot  = run;
    float rtot = 1.f / fmaxf(tot, 1e-30f);

    float g = gammas[h];
    float gamma = -log1pf(__expf(g));

    float4 dvv[4];
    #pragma unroll
    for (int c = 0; c < 4; c++)
        if (c < nc4) dvv[c] = *(const float4*)(dvrow + c * 128 + lane * 4);

    float sum2 = 0.f;
    #pragma unroll
    for (int c = 0; c < 4; c++) {
        if (c < nc4) {
            int j0 = c * 128 + lane * 4;
            bool full = (c < nfull);
            float e[4];
            float sc[4] = {scv[c].x, scv[c].y, scv[c].z, scv[c].w};
            float cu[4] = {s2v[c].x, s2v[c].y, s2v[c].z, s2v[c].w};
            float dv[4] = {dvv[c].x, dvv[c].y, dvv[c].z, dvv[c].w};
            #pragma unroll
            for (int e4 = 0; e4 < 4; e4++) {
                int j = j0 + e4;
                float rem  = fmaxf(tot - cu[e4], 0.f) * rtot;
                float pos  = (float)(i - j);
                float dist = sqrtf(fmaxf(rem * pos, 0.f));
                float eff  = fmaxf(__expf(dist * gamma * dv[e4]), 1e-5f);
                float s2 = sc[e4] * eff;
                float ev = __expf(s2);
                e[e4] = (full || j <= i) ? ev : 0.f;
                sum2 += e[e4];
            }
            s2v[c] = make_float4(e[0], e[1], e[2], e[3]);
        }
    }
    #pragma unroll
    for (int o = 16; o > 0; o >>= 1) sum2 += __shfl_xor_sync(0xFFFFFFFFu, sum2, o);

    float rs = (i == 0) ? 0.f : 1.f / sum2;

    __half* ph = g_phi + ((size_t)z * S_ + i) * S_;
    __half* pl = g_plo + ((size_t)z * S_ + i) * S_;
    #pragma unroll
    for (int c = 0; c < 4; c++) {
        if (c < nc4) {
            int j0 = c * 128 + lane * 4;
            float p0 = s2v[c].x * rs, p1 = s2v[c].y * rs;
            float p2 = s2v[c].z * rs, p3 = s2v[c].w * rs;
            uint32_t h01 = pack_f16(p0, p1), h23 = pack_f16(p2, p3);
            __half2 hh01 = *(__half2*)&h01;
            __half2 hh23 = *(__half2*)&h23;
            uint32_t l01 = pack_f16(p0 - __half2float(hh01.x),
                                    p1 - __half2float(hh01.y));
            uint32_t l23 = pack_f16(p2 - __half2float(hh23.x),
                                    p3 - __half2float(hh23.y));
            *(uint2*)(ph + j0) = make_uint2(h01, h23);
            *(uint2*)(pl + j0) = make_uint2(l01, l23);
        }
    }
}

// ==================================================================================
// PV via MMA, fp16 2-pass, occ 2. V staged at 74-half pitch (bank-conflict fix).
// SMEM: sPh 4608 + sPl 4608 + sVh 2368 words = 46336 B.
// ==================================================================================
#define PVV 37   // V pitch in words (74 halves)

__global__ __launch_bounds__(256, 2)
void pv_mma()
{
    extern __shared__ __align__(16) uint32_t sm[];
    uint32_t* sPh = sm;
    uint32_t* sPl = sm + 4608;
    uint32_t* sVh = sm + 9216;
    __half* sVh16 = (__half*)sVh;

    int z  = blockIdx.y;
    int b  = z >> 4, h = z & 15;
    int m0 = (3 - (int)blockIdx.x) * 128;

    int tid = threadIdx.x, lane = tid & 31, wid = tid >> 5;
    int wm = wid >> 2, wn = wid & 3, lq = lane >> 2, tq = lane & 3;

    const uint32_t* pwh = (const uint32_t*)(g_phi + (size_t)z * S_ * S_);
    const uint32_t* pwl = (const uint32_t*)(g_plo + (size_t)z * S_ * S_);
    const uint32_t* vwh = (const uint32_t*)(g_vhh + (size_t)z * S_ * DH_);

    float acc[4][2][4];
    #pragma unroll
    for (int mt = 0; mt < 4; mt++)
        #pragma unroll
        for (int nt = 0; nt < 2; nt++)
            #pragma unroll
            for (int e = 0; e < 4; e++) acc[mt][nt][e] = 0.f;

    int nchunks = m0 / 64 + 2;

    for (int c = 0; c < nchunks; c++) {
        int k0 = c * 64;
        {
            int row = tid >> 1, hf = tid & 1;
            int gofs = (m0 + row) * 256 + k0 / 2 + hf * 16;
            int so = row * PADS + hf * 16;
            #pragma unroll
            for (int qd = 0; qd < 4; qd++) {
                *(uint4*)(sPh + so + qd * 4) = *(const uint4*)(pwh + gofs + qd * 4);
                *(uint4*)(sPl + so + qd * 4) = *(const uint4*)(pwl + gofs + qd * 4);
            }
        }
        {
            int r  = tid >> 2;
            int w0 = (tid & 3) * 8;
            #pragma unroll
            for (int qd = 0; qd < 2; qd++) {
                uint4 vv = *(const uint4*)(vwh + (k0 + r) * 32 + w0 + qd * 4);
                uint32_t wv[4] = {vv.x, vv.y, vv.z, vv.w};
                #pragma unroll
                for (int q2 = 0; q2 < 4; q2++) {
                    int d0 = (w0 + qd * 4 + q2) * 2;
                    __half2 pr = *(__half2*)&wv[q2];
                    sVh16[d0 * 74 + r]       = pr.x;
                    sVh16[(d0 + 1) * 74 + r] = pr.y;
                }
            }
        }
        __syncthreads();

        #pragma unroll
        for (int ks = 0; ks < 4; ks++) {
            int kofs = ks * 8 + tq;
            uint32_t bh[2][2];
            #pragma unroll
            for (int nt = 0; nt < 2; nt++) {
                int bi = (wn * 16 + nt * 8 + lq) * PVV + kofs;
                bh[nt][0] = sVh[bi]; bh[nt][1] = sVh[bi + 4];
            }
            #pragma unroll
            for (int mt = 0; mt < 4; mt++) {
                int ai = (wm * 64 + mt * 16 + lq) * PADS + kofs;
                uint32_t ah0 = sPh[ai],     ah1 = sPh[ai + 8 * PADS];
                uint32_t ah2 = sPh[ai + 4], ah3 = sPh[ai + 8 * PADS + 4];
                uint32_t al0 = sPl[ai],     al1 = sPl[ai + 8 * PADS];
                uint32_t al2 = sPl[ai + 4], al3 = sPl[ai + 8 * PADS + 4];
                #pragma unroll
                for (int nt = 0; nt < 2; nt++) {
                    mma_f16(acc[mt][nt], ah0, ah1, ah2, ah3, bh[nt][0], bh[nt][1]);
                    mma_f16(acc[mt][nt], al0, al1, al2, al3, bh[nt][0], bh[nt][1]);
                }
            }
        }
        __syncthreads();
    }

    #pragma unroll
    for (int mt = 0; mt < 4; mt++) {
        #pragma unroll
        for (int nt = 0; nt < 2; nt++) {
            int d = wn * 16 + nt * 8 + tq * 2;
            #pragma unroll
            for (int hf = 0; hf < 2; hf++) {
                int i = m0 + wm * 64 + mt * 16 + lq + hf * 8;
                *(float2*)&g_att[((size_t)b * S_ + i) * D_ + h * DH_ + d] =
                    make_float2(acc[mt][nt][hf * 2], acc[mt][nt][hf * 2 + 1]);
            }
        }
    }
}

// ==================================================================================
extern "C" void kernel_launch(void* const* d_in, const int* in_sizes, int n_in,
                              void* d_out, int out_size)
{
    const float* q      = (const float*)d_in[0];
    const float* k      = (const float*)d_in[1];
    const float* v      = (const float*)d_in[2];
    const float* pdiff  = (const float*)d_in[3];
    const float* Wk     = (const float*)d_in[4];
    const float* bk     = (const float*)d_in[5];
    const float* Wv     = (const float*)d_in[6];
    const float* bv     = (const float*)d_in[7];
    const float* Wo     = (const float*)d_in[8];
    const float* bo     = (const float*)d_in[9];
    const float* gammas = (const float*)d_in[10];
    float* out = (float*)d_out;

    float* att;
    cudaGetSymbolAddress((void**)&att, g_att);

    cudaFuncSetAttribute(gemm_qkv,   cudaFuncAttributeMaxDynamicSharedMemorySize, 81920);
    cudaFuncSetAttribute(gemm_out,   cudaFuncAttributeMaxDynamicSharedMemorySize, 81920);
    cudaFuncSetAttribute(scores_mma, cudaFuncAttributeMaxDynamicSharedMemorySize, 73728);
    cudaFuncSetAttribute(pv_mma,     cudaFuncAttributeMaxDynamicSharedMemorySize, 46336);

    gemm_qkv<<<dim3(8, 32, 4), 512, 81920>>>(q, k, v, Wk, bk, Wv, bv, pdiff);

    scores_mma<<<dim3(10, BH_), 256, 73728>>>();

    row_kernel<<<dim3(S_ / 8, BH_), 256>>>(gammas);

    pv_mma<<<dim3(4, BH_), 256, 46336>>>();

    gemm_out<<<dim3(8, 32), 512, 81920>>>(att, Wo, bo, out);
}